// round 2
// baseline (speedup 1.0000x reference)
#include <cuda_runtime.h>

// MANN_Attn: 2 DNC encoders (512 steps) + attention DNC decoder (400 steps).
// Persistent-CTA design: each CTA owns 2 batch elements across the whole scan.

#define B_ 64
#define OUT_ 153

static __device__ float g_o1[16 * B_ * 32 * 64]; // [t][b][l][e]
static __device__ float g_o2[16 * B_ * 32 * 64];

__device__ __forceinline__ float sigf(float x) { return 1.0f / (1.0f + expf(-x)); }
__device__ __forceinline__ float softplusf(float x) { return (x > 15.0f) ? x : log1pf(expf(x)); }

// ======================= Encoder =======================
struct EncP {
    const int* codes; const float* emb;
    const float *wx, *wh, *bx, *bh, *wi, *bi;
};

__global__ void __launch_bounds__(256, 1)
enc_kernel(EncP P0, EncP P1)
{
    const bool is0 = (blockIdx.x < 32);
    EncP p = is0 ? P0 : P1;
    float* o_out = is0 ? g_o1 : g_o2;
    const int b0 = (blockIdx.x & 31) * 2;
    const int tid = threadIdx.x;

    extern __shared__ float sm[];
    float* s_wx = sm;                // 24576 (128x192)
    float* s_wh = s_wx + 24576;      // 12288 (64x192)
    float* s_wi = s_wh + 12288;      // 16576 (64x259)
    float* s_bx = s_wi + 16576;      // 192
    float* s_bh = s_bx + 192;        // 192
    float* s_bi = s_bh + 192;        // 260
    float* s_x  = s_bi + 260;        // 256  [k][b] (x | r)
    float* s_h  = s_x + 256;         // 128  [j][b]
    float* s_gx = s_h + 128;         // 384
    float* s_gh = s_gx + 384;        // 384
    float* s_if = s_gh + 384;        // 520
    float* s_M  = s_if + 520;        // 2048 [b][n][e]
    float* s_mn = s_M + 2048;        // 32
    float* s_md = s_mn + 32;         // 32
    float* s_w  = s_md + 32;         // 32
    float* s_kn = s_w + 32;          // 8

    for (int i = tid; i < 24576; i += 256) s_wx[i] = p.wx[i];
    for (int i = tid; i < 12288; i += 256) s_wh[i] = p.wh[i];
    for (int i = tid; i < 16576; i += 256) s_wi[i] = p.wi[i];
    if (tid < 192) { s_bx[tid] = p.bx[tid]; s_bh[tid] = p.bh[tid]; }
    for (int i = tid; i < 259; i += 256) s_bi[i] = p.bi[i];
    if (tid < 256) s_x[tid] = 0.0f;
    if (tid < 128) s_h[tid] = 0.0f;
    for (int i = tid; i < 2048; i += 256) s_M[i] = 0.0f;
    __syncthreads();

    const int c  = tid & 7;          // 8 lanes per cell
    const int pq = tid >> 3;         // 0..31 = b*16+n
    const int pb = pq >> 4, pn = pq & 15;
    float* Mp = s_M + (pb * 16 + pn) * 64 + c * 8;

    for (int s = 0; s < 512; ++s) {
        if (tid < 128) {             // x = emb[code]
            int b = tid & 1, e = tid >> 1;
            int code = p.codes[(b0 + b) * 512 + s];
            s_x[e * 2 + b] = p.emb[code * 64 + e];
        }
        __syncthreads();
        if (tid < 192) {             // gx = [x,r]@wx+bx ; gh = h@wh+bh
            float a0 = 0.f, a1 = 0.f, h0 = 0.f, h1 = 0.f;
            const float* wc = s_wx + tid;
            #pragma unroll 8
            for (int k = 0; k < 128; k++) {
                float w = wc[k * 192]; float2 x = *(const float2*)(s_x + 2 * k);
                a0 += w * x.x; a1 += w * x.y;
            }
            const float* hc = s_wh + tid;
            #pragma unroll 8
            for (int k = 0; k < 64; k++) {
                float w = hc[k * 192]; float2 h = *(const float2*)(s_h + 2 * k);
                h0 += w * h.x; h1 += w * h.y;
            }
            float bxv = s_bx[tid], bhv = s_bh[tid];
            s_gx[tid * 2] = a0 + bxv; s_gx[tid * 2 + 1] = a1 + bxv;
            s_gh[tid * 2] = h0 + bhv; s_gh[tid * 2 + 1] = h1 + bhv;
        }
        __syncthreads();
        if (tid < 128) {             // GRU
            int b = tid & 1, j = tid >> 1;
            float xr = s_gx[j*2+b], xz = s_gx[(64+j)*2+b], xn = s_gx[(128+j)*2+b];
            float hr = s_gh[j*2+b], hz = s_gh[(64+j)*2+b], hn = s_gh[(128+j)*2+b];
            float rg = sigf(xr + hr), z = sigf(xz + hz);
            float n = tanhf(xn + rg * hn);
            s_h[j*2+b] = (1.0f - z) * n + z * s_h[j*2+b];
        }
        __syncthreads();
        for (int j = tid; j < 259; j += 256) {   // iface = h@wi+bi
            float a0 = 0.f, a1 = 0.f;
            const float* wc = s_wi + j;
            #pragma unroll 8
            for (int k = 0; k < 64; k++) {
                float w = wc[k * 259]; float2 h = *(const float2*)(s_h + 2 * k);
                a0 += w * h.x; a1 += w * h.y;
            }
            float bv = s_bi[j];
            s_if[j * 2] = a0 + bv; s_if[j * 2 + 1] = a1 + bv;
        }
        __syncthreads();
        {                            // pre-update M stats: ||M_n||, M_n.k_w
            float ss = 0.f, dw = 0.f;
            #pragma unroll
            for (int i = 0; i < 8; i++) {
                float m = Mp[i];
                ss += m * m; dw += m * s_if[(64 + c * 8 + i) * 2 + pb];
            }
            for (int d = 4; d > 0; d >>= 1) {
                ss += __shfl_down_sync(0xffffffffu, ss, d);
                dw += __shfl_down_sync(0xffffffffu, dw, d);
            }
            if (c == 0) { s_mn[pq] = sqrtf(ss); s_md[pq] = dw; }
        }
        if (tid < 128) {             // key norms: isr=0 -> k_w, isr=1 -> k_r
            int warp = tid >> 5, lane = tid & 31;
            int b = warp & 1, isr = warp >> 1;
            int base = isr ? 0 : 64;
            float v0 = s_if[(base + lane) * 2 + b], v1 = s_if[(base + 32 + lane) * 2 + b];
            float t2 = v0 * v0 + v1 * v1;
            for (int d = 16; d > 0; d >>= 1) t2 += __shfl_down_sync(0xffffffffu, t2, d);
            if (lane == 0) s_kn[isr * 2 + b] = sqrtf(t2);
        }
        __syncthreads();
        if (tid < 2) {               // ww = g_w * softmax(beta_w * cos_w)
            int b = tid;
            float bw = softplusf(s_if[257*2+b]) + 1.0f;
            float gw = sigf(s_if[258*2+b]);
            float kn = s_kn[0*2+b], sc[16], mx = -1e30f;
            #pragma unroll
            for (int n = 0; n < 16; n++) {
                sc[n] = bw * (s_md[b*16+n] / (s_mn[b*16+n] * kn + 1e-6f));
                mx = fmaxf(mx, sc[n]);
            }
            float sum = 0.f;
            #pragma unroll
            for (int n = 0; n < 16; n++) { sc[n] = expf(sc[n] - mx); sum += sc[n]; }
            float inv = gw / sum;
            #pragma unroll
            for (int n = 0; n < 16; n++) s_w[b*16+n] = sc[n] * inv;
        }
        __syncthreads();
        {                            // M update + post stats (dot k_r)
            float wwv = s_w[pq], ss = 0.f, dr = 0.f;
            #pragma unroll
            for (int i = 0; i < 8; i++) {
                int e = c * 8 + i;
                float er = sigf(s_if[(128 + e) * 2 + pb]);
                float wv = s_if[(192 + e) * 2 + pb];
                float m = Mp[i];
                m = m * (1.0f - wwv * er) + wwv * wv;
                Mp[i] = m;
                ss += m * m; dr += m * s_if[e * 2 + pb];
            }
            for (int d = 4; d > 0; d >>= 1) {
                ss += __shfl_down_sync(0xffffffffu, ss, d);
                dr += __shfl_down_sync(0xffffffffu, dr, d);
            }
            if (c == 0) { s_mn[pq] = sqrtf(ss); s_md[pq] = dr; }
        }
        __syncthreads();
        if (tid < 2) {               // wr = softmax(beta_r * cos_r)
            int b = tid;
            float br = softplusf(s_if[256*2+b]) + 1.0f;
            float kn = s_kn[1*2+b], sc[16], mx = -1e30f;
            #pragma unroll
            for (int n = 0; n < 16; n++) {
                sc[n] = br * (s_md[b*16+n] / (s_mn[b*16+n] * kn + 1e-6f));
                mx = fmaxf(mx, sc[n]);
            }
            float sum = 0.f;
            #pragma unroll
            for (int n = 0; n < 16; n++) { sc[n] = expf(sc[n] - mx); sum += sc[n]; }
            float inv = 1.0f / sum;
            #pragma unroll
            for (int n = 0; n < 16; n++) s_w[b*16+n] = sc[n] * inv;
        }
        __syncthreads();
        if (tid < 128) {             // r = wr@M ; emit h
            int b = tid & 1, e = tid >> 1;
            const float* Mb = s_M + b * 1024;
            float r = 0.f;
            #pragma unroll
            for (int n = 0; n < 16; n++) r += s_w[b*16+n] * Mb[n * 64 + e];
            s_x[(64 + e) * 2 + b] = r;
            o_out[(((s >> 5) * 64 + (b0 + b)) * 32 + (s & 31)) * 64 + e] = s_h[e * 2 + b];
        }
        __syncthreads();
    }
}

// ======================= Decoder =======================
struct DecP {
    const int* targets; const float* emb2;
    const float *wx, *wh, *bx, *bh, *wi, *bi;
    const float *attn0, *attn1, *combw, *combb, *outw, *outb;
    float* out;
};

__global__ void __launch_bounds__(384, 1)
dec_kernel(DecP p)
{
    const int b0 = blockIdx.x * 2;
    const int tid = threadIdx.x;

    extern __shared__ float sm[];
    float* s_wh = sm;                 // 49152 (128x384)
    float* s_x  = s_wh + 49152;       // 512  [k][b] (comb | r)
    float* s_h  = s_x + 512;          // 256
    float* s_gx = s_h + 256;          // 768
    float* s_gh = s_gx + 768;         // 768
    float* s_if = s_gh + 768;         // 1032
    float* s_M  = s_if + 1032;        // 4096 [b][n][w]
    float* s_c1 = s_M + 4096;         // 128
    float* s_c2 = s_c1 + 128;         // 128
    float* s_xe = s_c2 + 128;         // 128
    float* s_at = s_xe + 128;         // 128 [a][b][l]
    float* s_mn = s_at + 128;         // 32
    float* s_md = s_mn + 32;          // 32
    float* s_w  = s_md + 32;          // 32
    float* s_kn = s_w + 32;           // 8

    for (int i = tid; i < 49152; i += 384) s_wh[i] = p.wh[i];
    for (int i = tid; i < 512; i += 384) s_x[i] = 0.0f;
    for (int i = tid; i < 4096; i += 384) s_M[i] = 0.0f;
    if (tid < 256) {
        int b = tid & 1, e = tid >> 1;
        float h = (e < 64) ? g_o1[((b0 + b) * 32 + 31) * 64 + e]
                           : g_o2[((b0 + b) * 32 + 31) * 64 + (e - 64)];
        s_h[e * 2 + b] = h;
    }
    __syncthreads();

    const int c  = tid & 7;
    const int pq = tid >> 3;         // valid for tid<256
    const int pb = pq >> 4, pn = pq & 15;
    float* Mp = s_M + (pb * 16 + pn) * 128 + c * 16;

    for (int s = 0; s < 400; ++s) {
        const int v = s / 25, pos = s - v * 25;
        if (tid < 128) {             // token embedding
            int b = tid & 1, e = tid >> 1;
            int tok = (pos == 0) ? ((v == 0) ? 150 : 151)
                                 : p.targets[((b0 + b) * 16 + v) * 24 + (pos - 1)];
            s_xe[e * 2 + b] = __ldg(p.emb2 + tok * 64 + e);
        }
        if (tid < 256) {             // attention scores (h-term cancels)
            int cc = tid & 1, g = tid >> 1;
            int a = g >> 6, b = (g >> 5) & 1, l = g & 31;
            const float* op = (a ? g_o2 : g_o1) + ((v * 64 + (b0 + b)) * 32 + l) * 64 + cc * 32;
            const float* aw = (a ? p.attn1 : p.attn0) + 128 + cc * 32;
            float sc = 0.f;
            #pragma unroll
            for (int e = 0; e < 32; e++) sc += op[e] * __ldg(aw + e);
            sc += __shfl_down_sync(0xffffffffu, sc, 1);
            if (cc == 0) s_at[g] = sc;
        }
        __syncthreads();
        if (tid < 4) {               // softmax over l
            float* at = s_at + (tid >> 1) * 64 + (tid & 1) * 32;
            float mx = -1e30f;
            for (int l = 0; l < 32; l++) mx = fmaxf(mx, at[l]);
            float sum = 0.f;
            for (int l = 0; l < 32; l++) { float e2 = expf(at[l] - mx); at[l] = e2; sum += e2; }
            float inv = 1.0f / sum;
            for (int l = 0; l < 32; l++) at[l] *= inv;
        }
        __syncthreads();
        if (tid < 256) {             // contexts
            int a = tid >> 7, b = (tid >> 6) & 1, e = tid & 63;
            const float* op = (a ? g_o2 : g_o1) + ((v * 64 + (b0 + b)) * 32) * 64 + e;
            const float* at = s_at + a * 64 + b * 32;
            float cv = 0.f;
            #pragma unroll
            for (int l = 0; l < 32; l++) cv += at[l] * op[l * 64];
            (a ? s_c2 : s_c1)[e * 2 + b] = cv;
        }
        __syncthreads();
        if (tid < 128) {             // comb = relu([xe,c1,c2]@comb_w+b)
            int j = tid;
            float a0 = 0.f, a1 = 0.f;
            const float* w = p.combw + j;
            #pragma unroll 8
            for (int k = 0; k < 64; k++) {
                float wv = __ldg(w + k * 128); float2 x = *(const float2*)(s_xe + 2 * k);
                a0 += wv * x.x; a1 += wv * x.y;
            }
            #pragma unroll 8
            for (int k = 0; k < 64; k++) {
                float wv = __ldg(w + (64 + k) * 128); float2 x = *(const float2*)(s_c1 + 2 * k);
                a0 += wv * x.x; a1 += wv * x.y;
            }
            #pragma unroll 8
            for (int k = 0; k < 64; k++) {
                float wv = __ldg(w + (128 + k) * 128); float2 x = *(const float2*)(s_c2 + 2 * k);
                a0 += wv * x.x; a1 += wv * x.y;
            }
            float bb = __ldg(p.combb + j);
            s_x[j * 2] = fmaxf(a0 + bb, 0.f);
            s_x[j * 2 + 1] = fmaxf(a1 + bb, 0.f);
        }
        __syncthreads();
        {                            // gx / gh (all 384 threads, j=tid)
            int j = tid;
            float a0 = 0.f, a1 = 0.f;
            const float* w = p.wx + j;
            #pragma unroll 8
            for (int k = 0; k < 256; k++) {
                float wv = __ldg(w + k * 384); float2 x = *(const float2*)(s_x + 2 * k);
                a0 += wv * x.x; a1 += wv * x.y;
            }
            float bxv = __ldg(p.bx + j);
            s_gx[j * 2] = a0 + bxv; s_gx[j * 2 + 1] = a1 + bxv;
            float h0 = 0.f, h1 = 0.f;
            const float* wh2 = s_wh + j;
            #pragma unroll 8
            for (int k = 0; k < 128; k++) {
                float wv = wh2[k * 384]; float2 h = *(const float2*)(s_h + 2 * k);
                h0 += wv * h.x; h1 += wv * h.y;
            }
            float bhv = __ldg(p.bh + j);
            s_gh[j * 2] = h0 + bhv; s_gh[j * 2 + 1] = h1 + bhv;
        }
        __syncthreads();
        if (tid < 256) {             // GRU
            int b = tid & 1, j = tid >> 1;
            float xr = s_gx[j*2+b], xz = s_gx[(128+j)*2+b], xn = s_gx[(256+j)*2+b];
            float hr = s_gh[j*2+b], hz = s_gh[(128+j)*2+b], hn = s_gh[(256+j)*2+b];
            float rg = sigf(xr + hr), z = sigf(xz + hz);
            float n = tanhf(xn + rg * hn);
            s_h[j*2+b] = (1.0f - z) * n + z * s_h[j*2+b];
        }
        __syncthreads();
        for (int j = tid; j < 515; j += 384) {   // iface
            float a0 = 0.f, a1 = 0.f;
            const float* w = p.wi + j;
            #pragma unroll 8
            for (int k = 0; k < 128; k++) {
                float wv = __ldg(w + k * 515); float2 h = *(const float2*)(s_h + 2 * k);
                a0 += wv * h.x; a1 += wv * h.y;
            }
            float bv = __ldg(p.bi + j);
            s_if[j * 2] = a0 + bv; s_if[j * 2 + 1] = a1 + bv;
        }
        __syncthreads();
        if (tid < 256) {             // pre-update stats
            float ss = 0.f, dw = 0.f;
            #pragma unroll
            for (int i = 0; i < 16; i++) {
                float m = Mp[i];
                ss += m * m; dw += m * s_if[(128 + c * 16 + i) * 2 + pb];
            }
            for (int d = 4; d > 0; d >>= 1) {
                ss += __shfl_down_sync(0xffffffffu, ss, d);
                dw += __shfl_down_sync(0xffffffffu, dw, d);
            }
            if (c == 0) { s_mn[pq] = sqrtf(ss); s_md[pq] = dw; }
        }
        if (tid < 128) {             // key norms (128-dim)
            int warp = tid >> 5, lane = tid & 31;
            int b = warp & 1, isr = warp >> 1;
            int base = isr ? 0 : 128;
            float t2 = 0.f;
            #pragma unroll
            for (int q = 0; q < 4; q++) {
                float vq = s_if[(base + lane + q * 32) * 2 + b];
                t2 += vq * vq;
            }
            for (int d = 16; d > 0; d >>= 1) t2 += __shfl_down_sync(0xffffffffu, t2, d);
            if (lane == 0) s_kn[isr * 2 + b] = sqrtf(t2);
        }
        __syncthreads();
        if (tid < 2) {               // ww
            int b = tid;
            float bw = softplusf(s_if[513*2+b]) + 1.0f;
            float gw = sigf(s_if[514*2+b]);
            float kn = s_kn[0*2+b], sc[16], mx = -1e30f;
            #pragma unroll
            for (int n = 0; n < 16; n++) {
                sc[n] = bw * (s_md[b*16+n] / (s_mn[b*16+n] * kn + 1e-6f));
                mx = fmaxf(mx, sc[n]);
            }
            float sum = 0.f;
            #pragma unroll
            for (int n = 0; n < 16; n++) { sc[n] = expf(sc[n] - mx); sum += sc[n]; }
            float inv = gw / sum;
            #pragma unroll
            for (int n = 0; n < 16; n++) s_w[b*16+n] = sc[n] * inv;
        }
        __syncthreads();
        if (tid < 256) {             // M update + post stats
            float wwv = s_w[pq], ss = 0.f, dr = 0.f;
            #pragma unroll
            for (int i = 0; i < 16; i++) {
                int e = c * 16 + i;
                float er = sigf(s_if[(256 + e) * 2 + pb]);
                float wv = s_if[(384 + e) * 2 + pb];
                float m = Mp[i];
                m = m * (1.0f - wwv * er) + wwv * wv;
                Mp[i] = m;
                ss += m * m; dr += m * s_if[e * 2 + pb];
            }
            for (int d = 4; d > 0; d >>= 1) {
                ss += __shfl_down_sync(0xffffffffu, ss, d);
                dr += __shfl_down_sync(0xffffffffu, dr, d);
            }
            if (c == 0) { s_mn[pq] = sqrtf(ss); s_md[pq] = dr; }
        }
        __syncthreads();
        if (tid < 2) {               // wr
            int b = tid;
            float br = softplusf(s_if[512*2+b]) + 1.0f;
            float kn = s_kn[1*2+b], sc[16], mx = -1e30f;
            #pragma unroll
            for (int n = 0; n < 16; n++) {
                sc[n] = br * (s_md[b*16+n] / (s_mn[b*16+n] * kn + 1e-6f));
                mx = fmaxf(mx, sc[n]);
            }
            float sum = 0.f;
            #pragma unroll
            for (int n = 0; n < 16; n++) { sc[n] = expf(sc[n] - mx); sum += sc[n]; }
            float inv = 1.0f / sum;
            #pragma unroll
            for (int n = 0; n < 16; n++) s_w[b*16+n] = sc[n] * inv;
        }
        __syncthreads();
        if (tid < 256) {             // r = wr@M
            int b = tid & 1, e = tid >> 1;
            const float* Mb = s_M + b * 2048;
            float r = 0.f;
            #pragma unroll
            for (int n = 0; n < 16; n++) r += s_w[b*16+n] * Mb[n * 128 + e];
            s_x[(128 + e) * 2 + b] = r;
        }
        if (tid < 306) {             // logits = [h2,c1,c2]@out_w + out_b
            int b = tid & 1, j = tid >> 1;
            float acc = __ldg(p.outb + j);
            const float* w = p.outw + j;
            #pragma unroll 8
            for (int k = 0; k < 128; k++) acc += __ldg(w + k * 153) * s_h[k * 2 + b];
            #pragma unroll 8
            for (int k = 0; k < 64; k++)  acc += __ldg(w + (128 + k) * 153) * s_c1[k * 2 + b];
            #pragma unroll 8
            for (int k = 0; k < 64; k++)  acc += __ldg(w + (192 + k) * 153) * s_c2[k * 2 + b];
            p.out[((b0 + b) * 400 + s) * 153 + j] = acc;
        }
        __syncthreads();
    }
}

// ======= labels + tail copies =======
// out layout: [pre_out 64*400*153][labels 64*400][pre_tail 64*25*153][lab_tail 64*25]
__global__ void tail_kernel(const int* __restrict__ targets, float* __restrict__ out)
{
    int idx = blockIdx.x * blockDim.x + threadIdx.x;
    if (idx < 25600) {
        int b = idx / 400, ss = idx % 400;
        int t = ss / 25, j = ss % 25;
        float val = (j < 24) ? (float)targets[(b * 16 + t) * 24 + j]
                             : ((t == 15) ? 152.0f : 151.0f);
        out[3916800 + idx] = val;
        if (ss >= 375) out[4187200 + b * 25 + (ss - 375)] = val;
    }
    if (idx < 244800) {
        int b = idx / 3825, rem = idx % 3825;
        out[3942400 + idx] = out[(b * 400 + 375) * 153 + rem];
    }
}

extern "C" void kernel_launch(void* const* d_in, const int* in_sizes, int n_in,
                              void* d_out, int out_size)
{
    (void)in_sizes; (void)n_in; (void)out_size;
    const int*   codes1 = (const int*)d_in[0];
    const int*   codes2 = (const int*)d_in[1];
    const int*   targets= (const int*)d_in[2];
    const float* emb0 = (const float*)d_in[3];
    const float* emb1 = (const float*)d_in[4];
    const float* emb2 = (const float*)d_in[5];

    EncP P0 { codes1, emb0, (const float*)d_in[6],  (const float*)d_in[7],
              (const float*)d_in[8],  (const float*)d_in[9],
              (const float*)d_in[10], (const float*)d_in[11] };
    EncP P1 { codes2, emb1, (const float*)d_in[12], (const float*)d_in[13],
              (const float*)d_in[14], (const float*)d_in[15],
              (const float*)d_in[16], (const float*)d_in[17] };
    DecP D  { targets, emb2,
              (const float*)d_in[18], (const float*)d_in[19],
              (const float*)d_in[20], (const float*)d_in[21],
              (const float*)d_in[22], (const float*)d_in[23],
              (const float*)d_in[24], (const float*)d_in[25],
              (const float*)d_in[26], (const float*)d_in[27],
              (const float*)d_in[28], (const float*)d_in[29],
              (float*)d_out };

    static bool attr_done = false;
    if (!attr_done) {
        cudaFuncSetAttribute(enc_kernel, cudaFuncAttributeMaxDynamicSharedMemorySize, 231632);
        cudaFuncSetAttribute(dec_kernel, cudaFuncAttributeMaxDynamicSharedMemorySize, 228800);
        attr_done = true;
    }

    enc_kernel<<<64, 256, 231632>>>(P0, P1);
    dec_kernel<<<32, 384, 228800>>>(D);
    tail_kernel<<<(244800 + 255) / 256, 256>>>(targets, (float*)d_out);
}

// round 3
// speedup vs baseline: 1.7651x; 1.7651x over previous
#include <cuda_runtime.h>

// MANN_Attn: 2 DNC encoders (512 steps) + attention DNC decoder (400 steps).
// Split-k persistent CTAs: enc NB=1 (128 CTAs x 512 thr), dec NB=2 (32 x 768).

static __device__ float g_o1[16 * 64 * 32 * 64]; // [t][b][l][e]
static __device__ float g_o2[16 * 64 * 32 * 64];
static __device__ __align__(16) float g_wi_pad[128 * 516];   // dec wi padded
static __device__ __align__(16) float g_outw_pad[256 * 156]; // dec outw padded

__device__ __forceinline__ float sigf(float x) { return 1.0f / (1.0f + expf(-x)); }
__device__ __forceinline__ float softplusf(float x) { return (x > 15.0f) ? x : log1pf(expf(x)); }

__global__ void prep_kernel(const float* __restrict__ wi, const float* __restrict__ outw)
{
    int i = blockIdx.x * 256 + threadIdx.x;
    if (i < 128 * 516) { int k = i / 516, j = i % 516; g_wi_pad[i] = (j < 515) ? wi[k * 515 + j] : 0.f; }
    if (i < 256 * 156) { int k = i / 156, j = i % 156; g_outw_pad[i] = (j < 153) ? outw[k * 153 + j] : 0.f; }
}

// ======================= Encoder (NB=1) =======================
struct EncP {
    const int* codes; const float* emb;
    const float *wx, *wh, *bx, *bh, *wi, *bi;
};

__global__ void __launch_bounds__(512, 1)
enc_kernel(EncP P0, EncP P1)
{
    const bool is0 = (blockIdx.x < 64);
    EncP p = is0 ? P0 : P1;
    float* o_out = is0 ? g_o1 : g_o2;
    const int b = blockIdx.x & 63;
    const int tid = threadIdx.x;

    extern __shared__ float sm[];
    float* s_wx = sm;               // 24576 (128x192)
    float* s_wh = s_wx + 24576;     // 12288 (64x192)
    float* s_wi = s_wh + 12288;     // 16640 (64x260 padded)
    float* s_p  = s_wi + 16640;     // 2080 partial union
    float* s_x  = s_p + 2080;       // 128  [x(64)|r(64)]
    float* s_h  = s_x + 128;        // 64
    float* s_gx = s_h + 64;         // 192
    float* s_gh = s_gx + 192;       // 192
    float* s_if = s_gh + 192;       // 260
    float* s_M  = s_if + 260;       // 1024 (16x64)
    float* s_mn = s_M + 1024;       // 16
    float* s_md = s_mn + 16;        // 16
    float* s_w  = s_md + 16;        // 16
    float* s_kn = s_w + 16;         // 4

    for (int i = tid; i < 24576; i += 512) s_wx[i] = p.wx[i];
    for (int i = tid; i < 12288; i += 512) s_wh[i] = p.wh[i];
    for (int i = tid; i < 16640; i += 512) {
        int k = i / 260, j = i % 260;
        s_wi[i] = (j < 259) ? p.wi[k * 259 + j] : 0.f;
    }
    for (int i = tid; i < 128; i += 512) s_x[i] = 0.f;
    if (tid < 64) s_h[tid] = 0.f;
    for (int i = tid; i < 1024; i += 512) s_M[i] = 0.f;
    __syncthreads();

    float* p_gx = s_p;           // 8 x 192
    float* p_gh = s_p + 1536;    // 2 x 192
    float* p_if = s_p;           // 8 x 260 (reused later)

    const int c8 = tid & 7;
    const int pn = tid >> 3;     // <16 for tid<128
    float* Mp = s_M + pn * 64 + c8 * 8;

    for (int s = 0; s < 512; ++s) {
        if (tid < 64) {          // x = emb[code]
            int code = p.codes[b * 512 + s];
            s_x[tid] = p.emb[code * 64 + tid];
        }
        __syncthreads();
        if (tid < 384) {         // gx partials: 48 jq x 8 kq, 16 iters
            int jq = tid % 48, kq = tid / 48;
            float a0 = 0.f, a1 = 0.f, a2 = 0.f, a3 = 0.f;
            const float* wb = s_wx + kq * 16 * 192 + jq * 4;
            const float* xb = s_x + kq * 16;
            #pragma unroll
            for (int i = 0; i < 16; i++) {
                float4 w = *(const float4*)(wb + i * 192);
                float xk = xb[i];
                a0 += w.x * xk; a1 += w.y * xk; a2 += w.z * xk; a3 += w.w * xk;
            }
            *(float4*)(p_gx + kq * 192 + jq * 4) = make_float4(a0, a1, a2, a3);
        } else if (tid < 480) {  // gh partials: 48 jq x 2 kh, 32 iters
            int t2 = tid - 384;
            int jq = t2 % 48, kh = t2 / 48;
            float a0 = 0.f, a1 = 0.f, a2 = 0.f, a3 = 0.f;
            const float* wb = s_wh + kh * 32 * 192 + jq * 4;
            const float* hb = s_h + kh * 32;
            #pragma unroll
            for (int i = 0; i < 32; i++) {
                float4 w = *(const float4*)(wb + i * 192);
                float hk = hb[i];
                a0 += w.x * hk; a1 += w.y * hk; a2 += w.z * hk; a3 += w.w * hk;
            }
            *(float4*)(p_gh + kh * 192 + jq * 4) = make_float4(a0, a1, a2, a3);
        }
        __syncthreads();
        if (tid < 192) {         // reduce gx
            float a = __ldg(p.bx + tid);
            #pragma unroll
            for (int kq = 0; kq < 8; kq++) a += p_gx[kq * 192 + tid];
            s_gx[tid] = a;
        } else if (tid < 384) {  // reduce gh
            int j = tid - 192;
            s_gh[j] = p_gh[j] + p_gh[192 + j] + __ldg(p.bh + j);
        }
        __syncthreads();
        if (tid < 64) {          // GRU
            float xr = s_gx[tid], xz = s_gx[64 + tid], xn = s_gx[128 + tid];
            float hr = s_gh[tid], hz = s_gh[64 + tid], hn = s_gh[128 + tid];
            float rg = sigf(xr + hr), z = sigf(xz + hz);
            float n = tanhf(xn + rg * hn);
            s_h[tid] = (1.0f - z) * n + z * s_h[tid];
        }
        __syncthreads();
        for (int u = tid; u < 520; u += 512) {   // iface partials: 65 jq x 8 kq
            int jq = u % 65, kq = u / 65;
            float a0 = 0.f, a1 = 0.f, a2 = 0.f, a3 = 0.f;
            const float* wb = s_wi + kq * 8 * 260 + jq * 4;
            const float* hb = s_h + kq * 8;
            #pragma unroll
            for (int i = 0; i < 8; i++) {
                float4 w = *(const float4*)(wb + i * 260);
                float hk = hb[i];
                a0 += w.x * hk; a1 += w.y * hk; a2 += w.z * hk; a3 += w.w * hk;
            }
            *(float4*)(p_if + kq * 260 + jq * 4) = make_float4(a0, a1, a2, a3);
        }
        __syncthreads();
        if (tid < 260) {
            float a = (tid < 259) ? __ldg(p.bi + tid) : 0.f;
            #pragma unroll
            for (int kq = 0; kq < 8; kq++) a += p_if[kq * 260 + tid];
            s_if[tid] = a;
        }
        __syncthreads();
        if (tid < 128) {         // pre-update M stats: ||M_n||, M_n . k_w
            float ss = 0.f, dw = 0.f;
            #pragma unroll
            for (int i = 0; i < 8; i++) {
                float m = Mp[i];
                ss += m * m; dw += m * s_if[64 + c8 * 8 + i];
            }
            for (int d = 4; d > 0; d >>= 1) {
                ss += __shfl_down_sync(0xffffffffu, ss, d);
                dw += __shfl_down_sync(0xffffffffu, dw, d);
            }
            if (c8 == 0) { s_mn[pn] = sqrtf(ss); s_md[pn] = dw; }
        } else if (tid < 192) {  // key norms: isr 0 -> k_w, 1 -> k_r
            int isr = (tid >> 5) - 4, lane = tid & 31;
            int base = isr ? 0 : 64;
            float v0 = s_if[base + lane], v1 = s_if[base + 32 + lane];
            float t2 = v0 * v0 + v1 * v1;
            for (int d = 16; d > 0; d >>= 1) t2 += __shfl_down_sync(0xffffffffu, t2, d);
            if (lane == 0) s_kn[isr] = sqrtf(t2);
        }
        __syncthreads();
        if (tid == 0) {          // ww = g_w * softmax(beta_w * cos_w)
            float bw = softplusf(s_if[257]) + 1.0f;
            float gw = sigf(s_if[258]);
            float kn = s_kn[0], sc[16], mx = -1e30f;
            #pragma unroll
            for (int n = 0; n < 16; n++) {
                sc[n] = bw * (s_md[n] / (s_mn[n] * kn + 1e-6f));
                mx = fmaxf(mx, sc[n]);
            }
            float sum = 0.f;
            #pragma unroll
            for (int n = 0; n < 16; n++) { sc[n] = expf(sc[n] - mx); sum += sc[n]; }
            float inv = gw / sum;
            #pragma unroll
            for (int n = 0; n < 16; n++) s_w[n] = sc[n] * inv;
        }
        __syncthreads();
        if (tid < 128) {         // M update + post stats (dot k_r)
            float wwv = s_w[pn], ss = 0.f, dr = 0.f;
            #pragma unroll
            for (int i = 0; i < 8; i++) {
                int e = c8 * 8 + i;
                float er = sigf(s_if[128 + e]);
                float wv = s_if[192 + e];
                float m = Mp[i];
                m = m * (1.0f - wwv * er) + wwv * wv;
                Mp[i] = m;
                ss += m * m; dr += m * s_if[e];
            }
            for (int d = 4; d > 0; d >>= 1) {
                ss += __shfl_down_sync(0xffffffffu, ss, d);
                dr += __shfl_down_sync(0xffffffffu, dr, d);
            }
            if (c8 == 0) { s_mn[pn] = sqrtf(ss); s_md[pn] = dr; }
        }
        __syncthreads();
        if (tid == 0) {          // wr = softmax(beta_r * cos_r)
            float br = softplusf(s_if[256]) + 1.0f;
            float kn = s_kn[1], sc[16], mx = -1e30f;
            #pragma unroll
            for (int n = 0; n < 16; n++) {
                sc[n] = br * (s_md[n] / (s_mn[n] * kn + 1e-6f));
                mx = fmaxf(mx, sc[n]);
            }
            float sum = 0.f;
            #pragma unroll
            for (int n = 0; n < 16; n++) { sc[n] = expf(sc[n] - mx); sum += sc[n]; }
            float inv = 1.0f / sum;
            #pragma unroll
            for (int n = 0; n < 16; n++) s_w[n] = sc[n] * inv;
        }
        __syncthreads();
        if (tid < 64) {          // r = wr@M ; emit h
            float r = 0.f;
            #pragma unroll
            for (int n = 0; n < 16; n++) r += s_w[n] * s_M[n * 64 + tid];
            s_x[64 + tid] = r;
            o_out[(((s >> 5) * 64 + b) * 32 + (s & 31)) * 64 + tid] = s_h[tid];
        }
        __syncthreads();
    }
}

// ======================= Decoder (NB=2) =======================
struct DecP {
    const int* targets; const float* emb2;
    const float *wx, *wh, *bx, *bh, *wi, *bi;
    const float *attn0, *attn1, *combw, *combb, *outb;
    float* out;
};

__global__ void __launch_bounds__(768, 1)
dec_kernel(DecP p)
{
    const int b0 = blockIdx.x * 2;
    const int tid = threadIdx.x;

    extern __shared__ float sm[];
    float* s_p  = sm;            // 12288 partial union
    float* s_x  = s_p + 12288;   // 512  [comb(128)|r(128)] x 2b
    float* s_h  = s_x + 512;     // 256
    float* s_gx = s_h + 256;     // 768
    float* s_gh = s_gx + 768;    // 768
    float* s_if = s_gh + 768;    // 1032
    float* s_M  = s_if + 1032;   // 4096 (2b x 16 x 128)
    float* s_xc = s_M + 4096;    // 384  [xe(64)|c1(64)|c2(64)] x 2b
    float* s_xo = s_xc + 384;    // 512  [h2(128)|c1(64)|c2(64)] x 2b
    float* s_at = s_xo + 512;    // 128  [a][b][l]
    float* s_mn = s_at + 128;    // 32
    float* s_md = s_mn + 32;     // 32
    float* s_w  = s_md + 32;     // 32
    float* s_kn = s_w + 32;      // 8

    float* p_wx = s_p;           // 8 x 768
    float* p_wh = s_p + 6144;    // 8 x 768
    float* p_if = s_p;           // 8 x 1032
    float* p_out = s_p;          // 8 x 312
    float* p_cb = s_p;           // 8 x 256

    for (int i = tid; i < 512; i += 768) s_x[i] = 0.f;
    for (int i = tid; i < 4096; i += 768) s_M[i] = 0.f;
    if (tid < 256) {
        int b = tid & 1, e = tid >> 1;
        float h = (e < 64) ? g_o1[((b0 + b) * 32 + 31) * 64 + e]
                           : g_o2[((b0 + b) * 32 + 31) * 64 + (e - 64)];
        s_h[e * 2 + b] = h;
    }
    __syncthreads();

    const int c8 = tid & 7;
    const int pq = tid >> 3;     // <32 for tid<256
    const int pb = pq >> 4, pn = pq & 15;
    float* Mp = s_M + (pb * 16 + pn) * 128 + c8 * 16;

    for (int s = 0; s < 400; ++s) {
        const int v = s / 25, pos = s - v * 25;
        // S0: token embed + attention scores
        if (tid >= 512 && tid < 640) {
            int t2 = tid - 512;
            int b = t2 & 1, e = t2 >> 1;
            int tok = (pos == 0) ? ((v == 0) ? 150 : 151)
                                 : p.targets[((b0 + b) * 16 + v) * 24 + (pos - 1)];
            s_xc[e * 2 + b] = __ldg(p.emb2 + tok * 64 + e);
        }
        if (tid < 256) {
            int cc = tid & 1, g = tid >> 1;
            int a = g >> 6, b = (g >> 5) & 1, l = g & 31;
            const float* op = (a ? g_o2 : g_o1) + ((v * 64 + (b0 + b)) * 32 + l) * 64 + cc * 32;
            const float* aw = (a ? p.attn1 : p.attn0) + 128 + cc * 32;
            float sc = 0.f;
            #pragma unroll
            for (int e = 0; e < 32; e++) sc += op[e] * __ldg(aw + e);
            sc += __shfl_down_sync(0xffffffffu, sc, 1);
            if (cc == 0) s_at[g] = sc;
        }
        __syncthreads();
        // S1: softmax over l
        if (tid < 4) {
            float* at = s_at + (tid >> 1) * 64 + (tid & 1) * 32;
            float mx = -1e30f;
            for (int l = 0; l < 32; l++) mx = fmaxf(mx, at[l]);
            float sum = 0.f;
            for (int l = 0; l < 32; l++) { float e2 = expf(at[l] - mx); at[l] = e2; sum += e2; }
            float inv = 1.0f / sum;
            for (int l = 0; l < 32; l++) at[l] *= inv;
        }
        __syncthreads();
        // S2: contexts -> s_xc[64..192)
        if (tid < 256) {
            int a = tid >> 7, b = (tid >> 6) & 1, e = tid & 63;
            const float* op = (a ? g_o2 : g_o1) + ((v * 64 + (b0 + b)) * 32) * 64 + e;
            const float* at = s_at + a * 64 + b * 32;
            float cv = 0.f;
            #pragma unroll
            for (int l = 0; l < 32; l++) cv += at[l] * op[l * 64];
            s_xc[(64 + a * 64 + e) * 2 + b] = cv;
        }
        __syncthreads();
        // S3: comb partials: 32 jq x 8 kq, 24 iters
        if (tid < 256) {
            int jq = tid & 31, kq = tid >> 5;
            float a[4][2] = {};
            const float* wb = p.combw + kq * 24 * 128 + jq * 4;
            const float* xb = s_xc + kq * 48;
            #pragma unroll
            for (int i = 0; i < 24; i++) {
                float4 w = __ldg((const float4*)(wb + i * 128));
                float2 x = *(const float2*)(xb + 2 * i);
                a[0][0] += w.x * x.x; a[0][1] += w.x * x.y;
                a[1][0] += w.y * x.x; a[1][1] += w.y * x.y;
                a[2][0] += w.z * x.x; a[2][1] += w.z * x.y;
                a[3][0] += w.w * x.x; a[3][1] += w.w * x.y;
            }
            float* d = p_cb + kq * 256 + jq * 8;
            *(float4*)(d)     = make_float4(a[0][0], a[0][1], a[1][0], a[1][1]);
            *(float4*)(d + 4) = make_float4(a[2][0], a[2][1], a[3][0], a[3][1]);
        }
        __syncthreads();
        // S4: comb reduce + relu
        if (tid < 256) {
            int j = tid >> 1;
            float a = __ldg(p.combb + j);
            #pragma unroll
            for (int kq = 0; kq < 8; kq++) a += p_cb[kq * 256 + tid];
            s_x[tid] = fmaxf(a, 0.f);
        }
        __syncthreads();
        // S5: wx partials (96 jq x 8 kq, 32 iters) + wh partials (16 iters)
        {
            int jq = tid % 96, kq = tid / 96;
            float a[4][2] = {};
            const float* wb = p.wx + kq * 32 * 384 + jq * 4;
            const float* xb = s_x + kq * 64;
            #pragma unroll
            for (int i = 0; i < 32; i++) {
                float4 w = __ldg((const float4*)(wb + i * 384));
                float2 x = *(const float2*)(xb + 2 * i);
                a[0][0] += w.x * x.x; a[0][1] += w.x * x.y;
                a[1][0] += w.y * x.x; a[1][1] += w.y * x.y;
                a[2][0] += w.z * x.x; a[2][1] += w.z * x.y;
                a[3][0] += w.w * x.x; a[3][1] += w.w * x.y;
            }
            float* d = p_wx + kq * 768 + jq * 8;
            *(float4*)(d)     = make_float4(a[0][0], a[0][1], a[1][0], a[1][1]);
            *(float4*)(d + 4) = make_float4(a[2][0], a[2][1], a[3][0], a[3][1]);

            float g[4][2] = {};
            const float* wb2 = p.wh + kq * 16 * 384 + jq * 4;
            const float* hb = s_h + kq * 32;
            #pragma unroll
            for (int i = 0; i < 16; i++) {
                float4 w = __ldg((const float4*)(wb2 + i * 384));
                float2 h = *(const float2*)(hb + 2 * i);
                g[0][0] += w.x * h.x; g[0][1] += w.x * h.y;
                g[1][0] += w.y * h.x; g[1][1] += w.y * h.y;
                g[2][0] += w.z * h.x; g[2][1] += w.z * h.y;
                g[3][0] += w.w * h.x; g[3][1] += w.w * h.y;
            }
            float* d2 = p_wh + kq * 768 + jq * 8;
            *(float4*)(d2)     = make_float4(g[0][0], g[0][1], g[1][0], g[1][1]);
            *(float4*)(d2 + 4) = make_float4(g[2][0], g[2][1], g[3][0], g[3][1]);
        }
        __syncthreads();
        // S6: reduce gx/gh (768 entries each)
        {
            float a = __ldg(p.bx + (tid >> 1));
            float g = __ldg(p.bh + (tid >> 1));
            #pragma unroll
            for (int kq = 0; kq < 8; kq++) {
                a += p_wx[kq * 768 + tid];
                g += p_wh[kq * 768 + tid];
            }
            s_gx[tid] = a; s_gh[tid] = g;
        }
        __syncthreads();
        // S7: GRU
        if (tid < 256) {
            int b = tid & 1, j = tid >> 1;
            float xr = s_gx[j*2+b], xz = s_gx[(128+j)*2+b], xn = s_gx[(256+j)*2+b];
            float hr = s_gh[j*2+b], hz = s_gh[(128+j)*2+b], hn = s_gh[(256+j)*2+b];
            float rg = sigf(xr + hr), z = sigf(xz + hz);
            float n = tanhf(xn + rg * hn);
            s_h[j*2+b] = (1.0f - z) * n + z * s_h[j*2+b];
        }
        __syncthreads();
        // S8: wi partials: 129 jq x 8 kq, 16 iters
        for (int u = tid; u < 1032; u += 768) {
            int jq = u % 129, kq = u / 129;
            float a[4][2] = {};
            const float* wb = g_wi_pad + kq * 16 * 516 + jq * 4;
            const float* hb = s_h + kq * 32;
            #pragma unroll
            for (int i = 0; i < 16; i++) {
                float4 w = *(const float4*)(wb + i * 516);
                float2 h = *(const float2*)(hb + 2 * i);
                a[0][0] += w.x * h.x; a[0][1] += w.x * h.y;
                a[1][0] += w.y * h.x; a[1][1] += w.y * h.y;
                a[2][0] += w.z * h.x; a[2][1] += w.z * h.y;
                a[3][0] += w.w * h.x; a[3][1] += w.w * h.y;
            }
            float* d = p_if + kq * 1032 + jq * 8;
            *(float4*)(d)     = make_float4(a[0][0], a[0][1], a[1][0], a[1][1]);
            *(float4*)(d + 4) = make_float4(a[2][0], a[2][1], a[3][0], a[3][1]);
        }
        __syncthreads();
        // S9: reduce iface + build s_xo
        for (int u = tid; u < 1030; u += 768) {
            float a = __ldg(p.bi + (u >> 1));
            #pragma unroll
            for (int kq = 0; kq < 8; kq++) a += p_if[kq * 1032 + u];
            s_if[u] = a;
        }
        for (int w2 = tid; w2 < 512; w2 += 768)
            s_xo[w2] = (w2 < 256) ? s_h[w2] : s_xc[w2 - 128];
        __syncthreads();
        // S10: M pre-stats + key norms + outw partials
        if (tid < 256) {
            float ss = 0.f, dw = 0.f;
            #pragma unroll
            for (int i = 0; i < 16; i++) {
                float m = Mp[i];
                ss += m * m; dw += m * s_if[(128 + c8 * 16 + i) * 2 + pb];
            }
            for (int d = 4; d > 0; d >>= 1) {
                ss += __shfl_down_sync(0xffffffffu, ss, d);
                dw += __shfl_down_sync(0xffffffffu, dw, d);
            }
            if (c8 == 0) { s_mn[pq] = sqrtf(ss); s_md[pq] = dw; }
        }
        if (tid < 128) {
            int warp = tid >> 5, lane = tid & 31;
            int b = warp & 1, isr = warp >> 1;
            int base = isr ? 0 : 128;
            float t2 = 0.f;
            #pragma unroll
            for (int q = 0; q < 4; q++) {
                float vq = s_if[(base + lane + q * 32) * 2 + b];
                t2 += vq * vq;
            }
            for (int d = 16; d > 0; d >>= 1) t2 += __shfl_down_sync(0xffffffffu, t2, d);
            if (lane == 0) s_kn[isr * 2 + b] = sqrtf(t2);
        }
        if (tid >= 384 && tid < 696) {   // outw partials: 39 jq x 8 kq, 32 iters
            int u = tid - 384;
            int jq = u % 39, kq = u / 39;
            float a[4][2] = {};
            const float* wb = g_outw_pad + kq * 32 * 156 + jq * 4;
            const float* xb = s_xo + kq * 64;
            #pragma unroll
            for (int i = 0; i < 32; i++) {
                float4 w = *(const float4*)(wb + i * 156);
                float2 x = *(const float2*)(xb + 2 * i);
                a[0][0] += w.x * x.x; a[0][1] += w.x * x.y;
                a[1][0] += w.y * x.x; a[1][1] += w.y * x.y;
                a[2][0] += w.z * x.x; a[2][1] += w.z * x.y;
                a[3][0] += w.w * x.x; a[3][1] += w.w * x.y;
            }
            float* d = p_out + kq * 312 + jq * 8;
            *(float4*)(d)     = make_float4(a[0][0], a[0][1], a[1][0], a[1][1]);
            *(float4*)(d + 4) = make_float4(a[2][0], a[2][1], a[3][0], a[3][1]);
        }
        __syncthreads();
        // S11: ww softmax + outw reduce/store
        if (tid < 2) {
            int b = tid;
            float bw = softplusf(s_if[513*2+b]) + 1.0f;
            float gw = sigf(s_if[514*2+b]);
            float kn = s_kn[0*2+b], sc[16], mx = -1e30f;
            #pragma unroll
            for (int n = 0; n < 16; n++) {
                sc[n] = bw * (s_md[b*16+n] / (s_mn[b*16+n] * kn + 1e-6f));
                mx = fmaxf(mx, sc[n]);
            }
            float sum = 0.f;
            #pragma unroll
            for (int n = 0; n < 16; n++) { sc[n] = expf(sc[n] - mx); sum += sc[n]; }
            float inv = gw / sum;
            #pragma unroll
            for (int n = 0; n < 16; n++) s_w[b*16+n] = sc[n] * inv;
        }
        if (tid >= 32 && tid < 338) {
            int idx = tid - 32;
            int j = idx >> 1, b = idx & 1;
            float a = __ldg(p.outb + j);
            #pragma unroll
            for (int kq = 0; kq < 8; kq++) a += p_out[kq * 312 + idx];
            p.out[((b0 + b) * 400 + s) * 153 + j] = a;
        }
        __syncthreads();
        // S12: M update + post stats
        if (tid < 256) {
            float wwv = s_w[pq], ss = 0.f, dr = 0.f;
            #pragma unroll
            for (int i = 0; i < 16; i++) {
                int e = c8 * 16 + i;
                float er = sigf(s_if[(256 + e) * 2 + pb]);
                float wv = s_if[(384 + e) * 2 + pb];
                float m = Mp[i];
                m = m * (1.0f - wwv * er) + wwv * wv;
                Mp[i] = m;
                ss += m * m; dr += m * s_if[e * 2 + pb];
            }
            for (int d = 4; d > 0; d >>= 1) {
                ss += __shfl_down_sync(0xffffffffu, ss, d);
                dr += __shfl_down_sync(0xffffffffu, dr, d);
            }
            if (c8 == 0) { s_mn[pq] = sqrtf(ss); s_md[pq] = dr; }
        }
        __syncthreads();
        // S13: wr softmax
        if (tid < 2) {
            int b = tid;
            float br = softplusf(s_if[512*2+b]) + 1.0f;
            float kn = s_kn[1*2+b], sc[16], mx = -1e30f;
            #pragma unroll
            for (int n = 0; n < 16; n++) {
                sc[n] = br * (s_md[b*16+n] / (s_mn[b*16+n] * kn + 1e-6f));
                mx = fmaxf(mx, sc[n]);
            }
            float sum = 0.f;
            #pragma unroll
            for (int n = 0; n < 16; n++) { sc[n] = expf(sc[n] - mx); sum += sc[n]; }
            float inv = 1.0f / sum;
            #pragma unroll
            for (int n = 0; n < 16; n++) s_w[b*16+n] = sc[n] * inv;
        }
        __syncthreads();
        // S14: r = wr@M
        if (tid < 256) {
            int b = tid & 1, e = tid >> 1;
            const float* Mb = s_M + b * 2048;
            float r = 0.f;
            #pragma unroll
            for (int n = 0; n < 16; n++) r += s_w[b*16+n] * Mb[n * 128 + e];
            s_x[(128 + e) * 2 + b] = r;
        }
        __syncthreads();
    }
}

// ======= labels + tail copies =======
__global__ void tail_kernel(const int* __restrict__ targets, float* __restrict__ out)
{
    int idx = blockIdx.x * blockDim.x + threadIdx.x;
    if (idx < 25600) {
        int b = idx / 400, ss = idx % 400;
        int t = ss / 25, j = ss % 25;
        float val = (j < 24) ? (float)targets[(b * 16 + t) * 24 + j]
                             : ((t == 15) ? 152.0f : 151.0f);
        out[3916800 + idx] = val;
        if (ss >= 375) out[4187200 + b * 25 + (ss - 375)] = val;
    }
    if (idx < 244800) {
        int b = idx / 3825, rem = idx % 3825;
        out[3942400 + idx] = out[(b * 400 + 375) * 153 + rem];
    }
}

extern "C" void kernel_launch(void* const* d_in, const int* in_sizes, int n_in,
                              void* d_out, int out_size)
{
    (void)in_sizes; (void)n_in; (void)out_size;
    const int*   codes1 = (const int*)d_in[0];
    const int*   codes2 = (const int*)d_in[1];
    const int*   targets= (const int*)d_in[2];

    EncP P0 { codes1, (const float*)d_in[3], (const float*)d_in[6],  (const float*)d_in[7],
              (const float*)d_in[8],  (const float*)d_in[9],
              (const float*)d_in[10], (const float*)d_in[11] };
    EncP P1 { codes2, (const float*)d_in[4], (const float*)d_in[12], (const float*)d_in[13],
              (const float*)d_in[14], (const float*)d_in[15],
              (const float*)d_in[16], (const float*)d_in[17] };
    DecP D  { targets, (const float*)d_in[5],
              (const float*)d_in[18], (const float*)d_in[19],
              (const float*)d_in[20], (const float*)d_in[21],
              (const float*)d_in[22], (const float*)d_in[23],
              (const float*)d_in[24], (const float*)d_in[25],
              (const float*)d_in[26], (const float*)d_in[27],
              (const float*)d_in[29],
              (float*)d_out };

    static bool attr_done = false;
    if (!attr_done) {
        cudaFuncSetAttribute(enc_kernel, cudaFuncAttributeMaxDynamicSharedMemorySize, 229984);
        cudaFuncSetAttribute(dec_kernel, cudaFuncAttributeMaxDynamicSharedMemorySize, 83392);
        attr_done = true;
    }

    prep_kernel<<<(128 * 516 + 255) / 256, 256>>>((const float*)d_in[22], (const float*)d_in[28]);
    enc_kernel<<<128, 512, 229984>>>(P0, P1);
    dec_kernel<<<32, 768, 83392>>>(D);
    tail_kernel<<<(244800 + 255) / 256, 256>>>(targets, (float*)d_out);
}

// round 4
// speedup vs baseline: 2.6590x; 1.5064x over previous
#include <cuda_runtime.h>

// MANN_Attn: 2 DNC encoders (512 steps) + attention DNC decoder (400 steps).
// R3: per-v hoisting of attention/contexts/cc-GEMV halves, token-table comb,
// warp-parallel softmaxes, wh-GEMV overlapped with comb phase.

static __device__ float g_o1[16 * 64 * 32 * 64]; // [t][b][l][e]
static __device__ float g_o2[16 * 64 * 32 * 64];
static __device__ __align__(16) float g_wi_pad[128 * 516];
static __device__ __align__(16) float g_outw_pad[256 * 156];
static __device__ __align__(16) float g_tbl[153 * 128];      // emb2 @ comb_w[0:64]

__device__ __forceinline__ float sigf(float x) { return 1.0f / (1.0f + expf(-x)); }
__device__ __forceinline__ float softplusf(float x) { return (x > 15.0f) ? x : log1pf(expf(x)); }

__global__ void prep_kernel(const float* __restrict__ wi, const float* __restrict__ outw,
                            const float* __restrict__ emb2, const float* __restrict__ combw)
{
    int i = blockIdx.x * 256 + threadIdx.x;
    if (i < 128 * 516) { int k = i / 516, j = i % 516; g_wi_pad[i] = (j < 515) ? wi[k * 515 + j] : 0.f; }
    if (i < 256 * 156) { int k = i / 156, j = i % 156; g_outw_pad[i] = (j < 153) ? outw[k * 153 + j] : 0.f; }
    if (i < 153 * 128) {
        int t = i / 128, j = i % 128;
        float a = 0.f;
        #pragma unroll 8
        for (int e = 0; e < 64; e++) a += emb2[t * 64 + e] * combw[e * 128 + j];
        g_tbl[i] = a;
    }
}

// ======================= Encoder (NB=1) =======================
struct EncP {
    const int* codes; const float* emb;
    const float *wx, *wh, *bx, *bh, *wi, *bi;
};

__global__ void __launch_bounds__(512, 1)
enc_kernel(EncP P0, EncP P1)
{
    const bool is0 = (blockIdx.x < 64);
    EncP p = is0 ? P0 : P1;
    float* o_out = is0 ? g_o1 : g_o2;
    const int b = blockIdx.x & 63;
    const int tid = threadIdx.x;

    extern __shared__ float sm[];
    float* s_wx = sm;               // 24576 (128x192)
    float* s_wh = s_wx + 24576;     // 12288 (64x192)
    float* s_wi = s_wh + 12288;     // 16640 (64x260 padded)
    float* s_p  = s_wi + 16640;     // 2304 partial union
    float* s_x  = s_p + 2304;       // 128  [x(64)|r(64)]
    float* s_h  = s_x + 128;        // 64
    float* s_gx = s_h + 64;         // 192
    float* s_gh = s_gx + 192;       // 192
    float* s_if = s_gh + 192;       // 260
    float* s_M  = s_if + 260;       // 1024 (16x64)
    float* s_mn = s_M + 1024;       // 16
    float* s_md = s_mn + 16;        // 16
    float* s_w  = s_md + 16;        // 16
    float* s_kn = s_w + 16;         // 4

    for (int i = tid; i < 24576; i += 512) s_wx[i] = p.wx[i];
    for (int i = tid; i < 12288; i += 512) s_wh[i] = p.wh[i];
    for (int i = tid; i < 16640; i += 512) {
        int k = i / 260, j = i % 260;
        s_wi[i] = (j < 259) ? p.wi[k * 259 + j] : 0.f;
    }
    if (tid < 128) s_x[tid] = 0.f;
    if (tid < 64) s_h[tid] = 0.f;
    for (int i = tid; i < 1024; i += 512) s_M[i] = 0.f;
    __syncthreads();

    float* p_gx = s_p;            // 8 x 192
    float* p_gh = s_p + 1536;     // 4 x 192
    float* p_if = s_p;            // 8 x 260 (reuse)

    const int c8 = tid & 7;
    const int pn = tid >> 3;
    float* Mp = s_M + pn * 64 + c8 * 8;

    for (int s = 0; s < 512; ++s) {
        // A: x load + gh partials (h_prev)
        if (tid < 64) {
            int code = p.codes[b * 512 + s];
            s_x[tid] = p.emb[code * 64 + tid];
        } else if (tid < 256) {
            int u = tid - 64;
            int jq = u % 48, kh = u / 48;     // 4 ksplits x 16 k
            float a0 = 0.f, a1 = 0.f, a2 = 0.f, a3 = 0.f;
            const float* wb = s_wh + kh * 16 * 192 + jq * 4;
            const float* hb = s_h + kh * 16;
            #pragma unroll
            for (int i = 0; i < 16; i++) {
                float4 w = *(const float4*)(wb + i * 192);
                float hk = hb[i];
                a0 += w.x * hk; a1 += w.y * hk; a2 += w.z * hk; a3 += w.w * hk;
            }
            *(float4*)(p_gh + kh * 192 + jq * 4) = make_float4(a0, a1, a2, a3);
        }
        __syncthreads();
        // B: gx partials
        if (tid < 384) {
            int jq = tid % 48, kq = tid / 48; // 8 ksplits x 16 k
            float a0 = 0.f, a1 = 0.f, a2 = 0.f, a3 = 0.f;
            const float* wb = s_wx + kq * 16 * 192 + jq * 4;
            const float* xb = s_x + kq * 16;
            #pragma unroll
            for (int i = 0; i < 16; i++) {
                float4 w = *(const float4*)(wb + i * 192);
                float xk = xb[i];
                a0 += w.x * xk; a1 += w.y * xk; a2 += w.z * xk; a3 += w.w * xk;
            }
            *(float4*)(p_gx + kq * 192 + jq * 4) = make_float4(a0, a1, a2, a3);
        }
        __syncthreads();
        // C: reduce
        if (tid < 192) {
            float a = __ldg(p.bx + tid);
            #pragma unroll
            for (int kq = 0; kq < 8; kq++) a += p_gx[kq * 192 + tid];
            s_gx[tid] = a;
        } else if (tid < 384) {
            int j = tid - 192;
            float a = __ldg(p.bh + j);
            #pragma unroll
            for (int kh = 0; kh < 4; kh++) a += p_gh[kh * 192 + j];
            s_gh[j] = a;
        }
        __syncthreads();
        if (tid < 64) {                      // GRU
            float xr = s_gx[tid], xz = s_gx[64 + tid], xn = s_gx[128 + tid];
            float hr = s_gh[tid], hz = s_gh[64 + tid], hn = s_gh[128 + tid];
            float rg = sigf(xr + hr), z = sigf(xz + hz);
            float n = tanhf(xn + rg * hn);
            s_h[tid] = (1.0f - z) * n + z * s_h[tid];
        }
        __syncthreads();
        for (int u = tid; u < 520; u += 512) {   // iface partials
            int jq = u % 65, kq = u / 65;
            float a0 = 0.f, a1 = 0.f, a2 = 0.f, a3 = 0.f;
            const float* wb = s_wi + kq * 8 * 260 + jq * 4;
            const float* hb = s_h + kq * 8;
            #pragma unroll
            for (int i = 0; i < 8; i++) {
                float4 w = *(const float4*)(wb + i * 260);
                float hk = hb[i];
                a0 += w.x * hk; a1 += w.y * hk; a2 += w.z * hk; a3 += w.w * hk;
            }
            *(float4*)(p_if + kq * 260 + jq * 4) = make_float4(a0, a1, a2, a3);
        }
        __syncthreads();
        if (tid < 260) {
            float a = (tid < 259) ? __ldg(p.bi + tid) : 0.f;
            #pragma unroll
            for (int kq = 0; kq < 8; kq++) a += p_if[kq * 260 + tid];
            s_if[tid] = a;
        }
        __syncthreads();
        if (tid < 128) {                     // pre-update M stats
            float ss = 0.f, dw = 0.f;
            #pragma unroll
            for (int i = 0; i < 8; i++) {
                float m = Mp[i];
                ss += m * m; dw += m * s_if[64 + c8 * 8 + i];
            }
            for (int d = 4; d > 0; d >>= 1) {
                ss += __shfl_down_sync(0xffffffffu, ss, d);
                dw += __shfl_down_sync(0xffffffffu, dw, d);
            }
            if (c8 == 0) { s_mn[pn] = sqrtf(ss); s_md[pn] = dw; }
        } else if (tid < 192) {              // key norms
            int isr = (tid >> 5) - 4, lane = tid & 31;
            int base = isr ? 0 : 64;
            float v0 = s_if[base + lane], v1 = s_if[base + 32 + lane];
            float t2 = v0 * v0 + v1 * v1;
            for (int d = 16; d > 0; d >>= 1) t2 += __shfl_down_sync(0xffffffffu, t2, d);
            if (lane == 0) s_kn[isr] = sqrtf(t2);
        }
        __syncthreads();
        if (tid < 16) {                      // ww (warp-parallel)
            float bw = softplusf(s_if[257]) + 1.0f;
            float gw = sigf(s_if[258]);
            float kn = s_kn[0];
            float sc = bw * (s_md[tid] / (s_mn[tid] * kn + 1e-6f));
            float mx = sc;
            for (int d = 8; d > 0; d >>= 1) mx = fmaxf(mx, __shfl_xor_sync(0xffffu, mx, d));
            float e = expf(sc - mx);
            float sum = e;
            for (int d = 8; d > 0; d >>= 1) sum += __shfl_xor_sync(0xffffu, sum, d);
            s_w[tid] = e * (gw / sum);
        }
        __syncthreads();
        if (tid < 128) {                     // M update + post stats
            float wwv = s_w[pn], ss = 0.f, dr = 0.f;
            #pragma unroll
            for (int i = 0; i < 8; i++) {
                int e = c8 * 8 + i;
                float er = sigf(s_if[128 + e]);
                float wv = s_if[192 + e];
                float m = Mp[i];
                m = m * (1.0f - wwv * er) + wwv * wv;
                Mp[i] = m;
                ss += m * m; dr += m * s_if[e];
            }
            for (int d = 4; d > 0; d >>= 1) {
                ss += __shfl_down_sync(0xffffffffu, ss, d);
                dr += __shfl_down_sync(0xffffffffu, dr, d);
            }
            if (c8 == 0) { s_mn[pn] = sqrtf(ss); s_md[pn] = dr; }
        }
        __syncthreads();
        if (tid < 16) {                      // wr (warp-parallel)
            float br = softplusf(s_if[256]) + 1.0f;
            float kn = s_kn[1];
            float sc = br * (s_md[tid] / (s_mn[tid] * kn + 1e-6f));
            float mx = sc;
            for (int d = 8; d > 0; d >>= 1) mx = fmaxf(mx, __shfl_xor_sync(0xffffu, mx, d));
            float e = expf(sc - mx);
            float sum = e;
            for (int d = 8; d > 0; d >>= 1) sum += __shfl_xor_sync(0xffffu, sum, d);
            s_w[tid] = e / sum;
        }
        __syncthreads();
        if (tid < 64) {                      // r = wr@M ; emit h
            float r = 0.f;
            #pragma unroll
            for (int n = 0; n < 16; n++) r += s_w[n] * s_M[n * 64 + tid];
            s_x[64 + tid] = r;
            o_out[(((s >> 5) * 64 + b) * 32 + (s & 31)) * 64 + tid] = s_h[tid];
        }
        __syncthreads();
    }
}

// ======================= Decoder (NB=2) =======================
struct DecP {
    const int* targets;
    const float *wx, *wh, *bx, *bh, *bi;
    const float *attn0, *attn1, *combw, *combb, *outb;
    float* out;
};

__global__ void __launch_bounds__(768, 1)
dec_kernel(DecP p)
{
    const int b0 = blockIdx.x * 2;
    const int tid = threadIdx.x;

    extern __shared__ float sm[];
    float* s_p  = sm;            // 12288 partial union
    float* s_x  = s_p + 12288;   // 512  [comb(128)|r(128)] x 2b
    float* s_h  = s_x + 512;     // 256
    float* s_gx = s_h + 256;     // 768
    float* s_gh = s_gx + 768;    // 768
    float* s_if = s_gh + 768;    // 1032
    float* s_M  = s_if + 1032;   // 4096 (2b x 16 x 128)
    float* s_c  = s_M + 4096;    // 256  [c1(64)|c2(64)] x 2b
    float* s_cc = s_c + 256;     // 256  per-v comb constant
    float* s_oc = s_cc + 256;    // 312  per-v out constant
    float* s_at = s_oc + 312;    // 128
    float* s_mn = s_at + 128;    // 32
    float* s_md = s_mn + 32;     // 32
    float* s_w  = s_md + 32;     // 32
    float* s_kn = s_w + 32;      // 8

    float* p_wx = s_p;           // 8 x 768
    float* p_wh = s_p + 6144;    // 4 x 768
    float* p_if = s_p;           // 4 x 1032
    float* p_oh = s_p + 4224;    // 4 x 312
    float* p_cb = s_p;           // 4 x 256 (per-v)
    float* p_oc = s_p + 1024;    // 4 x 312 (per-v)

    for (int i = tid; i < 512; i += 768) s_x[i] = 0.f;
    for (int i = tid; i < 4096; i += 768) s_M[i] = 0.f;
    if (tid < 256) {
        int b = tid & 1, e = tid >> 1;
        float h = (e < 64) ? g_o1[((b0 + b) * 32 + 31) * 64 + e]
                           : g_o2[((b0 + b) * 32 + 31) * 64 + (e - 64)];
        s_h[e * 2 + b] = h;
    }
    __syncthreads();

    const int c8 = tid & 7;
    const int pq = tid >> 3;
    const int pb = pq >> 4;
    float* Mp = s_M + pq * 128 + c8 * 16;   // pq<32: (b*16+n)

    for (int s = 0; s < 400; ++s) {
        const int v = s / 25, pos = s - v * 25;

        if (pos == 0) {
            // V0: attention scores
            if (tid < 256) {
                int cc = tid & 1, g = tid >> 1;
                int a = g >> 6, b = (g >> 5) & 1, l = g & 31;
                const float* op = (a ? g_o2 : g_o1) + ((v * 64 + (b0 + b)) * 32 + l) * 64 + cc * 32;
                const float* aw = (a ? p.attn1 : p.attn0) + 128 + cc * 32;
                float sc = 0.f;
                #pragma unroll
                for (int e = 0; e < 32; e++) sc += op[e] * __ldg(aw + e);
                sc += __shfl_down_sync(0xffffffffu, sc, 1);
                if (cc == 0) s_at[g] = sc;
            }
            __syncthreads();
            // V1: softmax (warp-parallel, 4 warps x 32 l)
            if (tid < 128) {
                int w = tid >> 5, l = tid & 31;
                float vsc = s_at[w * 32 + l];
                float mx = vsc;
                for (int d = 16; d > 0; d >>= 1) mx = fmaxf(mx, __shfl_xor_sync(0xffffffffu, mx, d));
                float e2 = expf(vsc - mx);
                float sum = e2;
                for (int d = 16; d > 0; d >>= 1) sum += __shfl_xor_sync(0xffffffffu, sum, d);
                s_at[w * 32 + l] = e2 / sum;
            }
            __syncthreads();
            // V2: contexts -> s_c
            if (tid < 256) {
                int a = tid >> 7, b = (tid >> 6) & 1, e = tid & 63;
                const float* op = (a ? g_o2 : g_o1) + ((v * 64 + (b0 + b)) * 32) * 64 + e;
                const float* at = s_at + a * 64 + b * 32;
                float cv = 0.f;
                #pragma unroll
                for (int l = 0; l < 32; l++) cv += at[l] * op[l * 64];
                s_c[(a * 64 + e) * 2 + b] = cv;
            }
            __syncthreads();
            // V3: comb_cc partials + out_cc partials
            if (tid < 128) {
                int jq = tid & 31, kq = tid >> 5;     // 4 x 32 k
                float a[4][2] = {};
                const float* wb = p.combw + (64 + kq * 32) * 128 + jq * 4;
                const float* xb = s_c + kq * 64;
                #pragma unroll
                for (int i = 0; i < 32; i++) {
                    float4 w = __ldg((const float4*)(wb + i * 128));
                    float2 x = *(const float2*)(xb + 2 * i);
                    a[0][0] += w.x * x.x; a[0][1] += w.x * x.y;
                    a[1][0] += w.y * x.x; a[1][1] += w.y * x.y;
                    a[2][0] += w.z * x.x; a[2][1] += w.z * x.y;
                    a[3][0] += w.w * x.x; a[3][1] += w.w * x.y;
                }
                float* d = p_cb + kq * 256 + jq * 8;
                *(float4*)(d)     = make_float4(a[0][0], a[0][1], a[1][0], a[1][1]);
                *(float4*)(d + 4) = make_float4(a[2][0], a[2][1], a[3][0], a[3][1]);
            } else if (tid < 284) {
                int u = tid - 128;
                int jq = u % 39, kq = u / 39;         // 4 x 32 k
                float a[4][2] = {};
                const float* wb = g_outw_pad + (128 + kq * 32) * 156 + jq * 4;
                const float* xb = s_c + kq * 64;
                #pragma unroll
                for (int i = 0; i < 32; i++) {
                    float4 w = *(const float4*)(wb + i * 156);
                    float2 x = *(const float2*)(xb + 2 * i);
                    a[0][0] += w.x * x.x; a[0][1] += w.x * x.y;
                    a[1][0] += w.y * x.x; a[1][1] += w.y * x.y;
                    a[2][0] += w.z * x.x; a[2][1] += w.z * x.y;
                    a[3][0] += w.w * x.x; a[3][1] += w.w * x.y;
                }
                float* d = p_oc + kq * 312 + jq * 8;
                *(float4*)(d)     = make_float4(a[0][0], a[0][1], a[1][0], a[1][1]);
                *(float4*)(d + 4) = make_float4(a[2][0], a[2][1], a[3][0], a[3][1]);
            }
            __syncthreads();
            // V4: reduce cc / oc
            if (tid < 256) {
                float a = __ldg(p.combb + (tid >> 1));
                #pragma unroll
                for (int kq = 0; kq < 4; kq++) a += p_cb[kq * 256 + tid];
                s_cc[tid] = a;
            } else if (tid < 568) {
                int idx = tid - 256;
                int j = idx >> 1;
                float a = (j < 153) ? __ldg(p.outb + j) : 0.f;
                #pragma unroll
                for (int kq = 0; kq < 4; kq++) a += p_oc[kq * 312 + idx];
                s_oc[idx] = a;
            }
            __syncthreads();
        }

        // A: comb via token table + wh partials (h_prev)
        if (tid < 256) {
            int b = tid & 1, j = tid >> 1;
            int tok = (pos == 0) ? ((v == 0) ? 150 : 151)
                                 : p.targets[((b0 + b) * 16 + v) * 24 + (pos - 1)];
            s_x[tid] = fmaxf(__ldg(g_tbl + tok * 128 + j) + s_cc[tid], 0.f);
        } else if (tid < 640) {
            int u = tid - 256;
            int jq = u % 96, kq = u / 96;    // 4 ksplits x 32 k
            float g[4][2] = {};
            const float* wb = p.wh + kq * 32 * 384 + jq * 4;
            const float* hb = s_h + kq * 64;
            #pragma unroll
            for (int i = 0; i < 32; i++) {
                float4 w = __ldg((const float4*)(wb + i * 384));
                float2 h = *(const float2*)(hb + 2 * i);
                g[0][0] += w.x * h.x; g[0][1] += w.x * h.y;
                g[1][0] += w.y * h.x; g[1][1] += w.y * h.y;
                g[2][0] += w.z * h.x; g[2][1] += w.z * h.y;
                g[3][0] += w.w * h.x; g[3][1] += w.w * h.y;
            }
            float* d2 = p_wh + kq * 768 + jq * 8;
            *(float4*)(d2)     = make_float4(g[0][0], g[0][1], g[1][0], g[1][1]);
            *(float4*)(d2 + 4) = make_float4(g[2][0], g[2][1], g[3][0], g[3][1]);
        }
        __syncthreads();
        // B: wx partials
        {
            int jq = tid % 96, kq = tid / 96;   // 8 ksplits x 32 k
            float a[4][2] = {};
            const float* wb = p.wx + kq * 32 * 384 + jq * 4;
            const float* xb = s_x + kq * 64;
            #pragma unroll
            for (int i = 0; i < 32; i++) {
                float4 w = __ldg((const float4*)(wb + i * 384));
                float2 x = *(const float2*)(xb + 2 * i);
                a[0][0] += w.x * x.x; a[0][1] += w.x * x.y;
                a[1][0] += w.y * x.x; a[1][1] += w.y * x.y;
                a[2][0] += w.z * x.x; a[2][1] += w.z * x.y;
                a[3][0] += w.w * x.x; a[3][1] += w.w * x.y;
            }
            float* d = p_wx + kq * 768 + jq * 8;
            *(float4*)(d)     = make_float4(a[0][0], a[0][1], a[1][0], a[1][1]);
            *(float4*)(d + 4) = make_float4(a[2][0], a[2][1], a[3][0], a[3][1]);
        }
        __syncthreads();
        // C1: reduce gx/gh
        {
            float a = __ldg(p.bx + (tid >> 1));
            float g = __ldg(p.bh + (tid >> 1));
            #pragma unroll
            for (int kq = 0; kq < 8; kq++) a += p_wx[kq * 768 + tid];
            #pragma unroll
            for (int kq = 0; kq < 4; kq++) g += p_wh[kq * 768 + tid];
            s_gx[tid] = a; s_gh[tid] = g;
        }
        __syncthreads();
        // C2: GRU
        if (tid < 256) {
            int b = tid & 1, j = tid >> 1;
            float xr = s_gx[j*2+b], xz = s_gx[(128+j)*2+b], xn = s_gx[(256+j)*2+b];
            float hr = s_gh[j*2+b], hz = s_gh[(128+j)*2+b], hn = s_gh[(256+j)*2+b];
            float rg = sigf(xr + hr), z = sigf(xz + hz);
            float n = tanhf(xn + rg * hn);
            s_h[j*2+b] = (1.0f - z) * n + z * s_h[j*2+b];
        }
        __syncthreads();
        // D: wi partials + outw(h2) partials
        if (tid < 516) {
            int jq = tid % 129, kq = tid / 129;  // 4 ksplits x 32 k
            float a[4][2] = {};
            const float* wb = g_wi_pad + kq * 32 * 516 + jq * 4;
            const float* hb = s_h + kq * 64;
            #pragma unroll
            for (int i = 0; i < 32; i++) {
                float4 w = *(const float4*)(wb + i * 516);
                float2 h = *(const float2*)(hb + 2 * i);
                a[0][0] += w.x * h.x; a[0][1] += w.x * h.y;
                a[1][0] += w.y * h.x; a[1][1] += w.y * h.y;
                a[2][0] += w.z * h.x; a[2][1] += w.z * h.y;
                a[3][0] += w.w * h.x; a[3][1] += w.w * h.y;
            }
            float* d = p_if + kq * 1032 + jq * 8;
            *(float4*)(d)     = make_float4(a[0][0], a[0][1], a[1][0], a[1][1]);
            *(float4*)(d + 4) = make_float4(a[2][0], a[2][1], a[3][0], a[3][1]);
        } else if (tid < 672) {
            int u = tid - 516;
            int jq = u % 39, kq = u / 39;        // 4 ksplits x 32 k (k=0..127 -> h2)
            float a[4][2] = {};
            const float* wb = g_outw_pad + kq * 32 * 156 + jq * 4;
            const float* hb = s_h + kq * 64;
            #pragma unroll
            for (int i = 0; i < 32; i++) {
                float4 w = *(const float4*)(wb + i * 156);
                float2 h = *(const float2*)(hb + 2 * i);
                a[0][0] += w.x * h.x; a[0][1] += w.x * h.y;
                a[1][0] += w.y * h.x; a[1][1] += w.y * h.y;
                a[2][0] += w.z * h.x; a[2][1] += w.z * h.y;
                a[3][0] += w.w * h.x; a[3][1] += w.w * h.y;
            }
            float* d = p_oh + kq * 312 + jq * 8;
            *(float4*)(d)     = make_float4(a[0][0], a[0][1], a[1][0], a[1][1]);
            *(float4*)(d + 4) = make_float4(a[2][0], a[2][1], a[3][0], a[3][1]);
        }
        __syncthreads();
        // E: reduce iface + logits store
        for (int u = tid; u < 1030; u += 768) {
            float a = __ldg(p.bi + (u >> 1));
            #pragma unroll
            for (int kq = 0; kq < 4; kq++) a += p_if[kq * 1032 + u];
            s_if[u] = a;
        }
        if (tid < 306) {
            int j = tid >> 1, b = tid & 1;
            float a = s_oc[tid];
            #pragma unroll
            for (int kq = 0; kq < 4; kq++) a += p_oh[kq * 312 + tid];
            p.out[((b0 + b) * 400 + s) * 153 + j] = a;
        }
        __syncthreads();
        // F: M pre-stats + key norms
        if (tid < 256) {
            float ss = 0.f, dw = 0.f;
            #pragma unroll
            for (int i = 0; i < 16; i++) {
                float m = Mp[i];
                ss += m * m; dw += m * s_if[(128 + c8 * 16 + i) * 2 + pb];
            }
            for (int d = 4; d > 0; d >>= 1) {
                ss += __shfl_down_sync(0xffffffffu, ss, d);
                dw += __shfl_down_sync(0xffffffffu, dw, d);
            }
            if (c8 == 0) { s_mn[pq] = sqrtf(ss); s_md[pq] = dw; }
        } else if (tid < 384) {
            int w = (tid >> 5) - 8, lane = tid & 31;   // w: 0..3
            int b = w & 1, isr = w >> 1;
            int base = isr ? 0 : 128;
            float t2 = 0.f;
            #pragma unroll
            for (int q = 0; q < 4; q++) {
                float vq = s_if[(base + lane + q * 32) * 2 + b];
                t2 += vq * vq;
            }
            for (int d = 16; d > 0; d >>= 1) t2 += __shfl_down_sync(0xffffffffu, t2, d);
            if (lane == 0) s_kn[isr * 2 + b] = sqrtf(t2);
        }
        __syncthreads();
        // G: ww softmax (2 half-warps)
        if (tid < 64 && (tid & 31) < 16) {
            int b = tid >> 5, n = tid & 15;
            float bw = softplusf(s_if[513*2+b]) + 1.0f;
            float gw = sigf(s_if[514*2+b]);
            float kn = s_kn[0*2+b];
            float sc = bw * (s_md[b*16+n] / (s_mn[b*16+n] * kn + 1e-6f));
            float mx = sc;
            for (int d = 8; d > 0; d >>= 1) mx = fmaxf(mx, __shfl_xor_sync(0xffffu, mx, d));
            float e = expf(sc - mx);
            float sum = e;
            for (int d = 8; d > 0; d >>= 1) sum += __shfl_xor_sync(0xffffu, sum, d);
            s_w[b*16+n] = e * (gw / sum);
        }
        __syncthreads();
        // H: M update + post stats
        if (tid < 256) {
            float wwv = s_w[pq], ss = 0.f, dr = 0.f;
            #pragma unroll
            for (int i = 0; i < 16; i++) {
                int e = c8 * 16 + i;
                float er = sigf(s_if[(256 + e) * 2 + pb]);
                float wv = s_if[(384 + e) * 2 + pb];
                float m = Mp[i];
                m = m * (1.0f - wwv * er) + wwv * wv;
                Mp[i] = m;
                ss += m * m; dr += m * s_if[e * 2 + pb];
            }
            for (int d = 4; d > 0; d >>= 1) {
                ss += __shfl_down_sync(0xffffffffu, ss, d);
                dr += __shfl_down_sync(0xffffffffu, dr, d);
            }
            if (c8 == 0) { s_mn[pq] = sqrtf(ss); s_md[pq] = dr; }
        }
        __syncthreads();
        // I: wr softmax
        if (tid < 64 && (tid & 31) < 16) {
            int b = tid >> 5, n = tid & 15;
            float br = softplusf(s_if[512*2+b]) + 1.0f;
            float kn = s_kn[1*2+b];
            float sc = br * (s_md[b*16+n] / (s_mn[b*16+n] * kn + 1e-6f));
            float mx = sc;
            for (int d = 8; d > 0; d >>= 1) mx = fmaxf(mx, __shfl_xor_sync(0xffffu, mx, d));
            float e = expf(sc - mx);
            float sum = e;
            for (int d = 8; d > 0; d >>= 1) sum += __shfl_xor_sync(0xffffu, sum, d);
            s_w[b*16+n] = e / sum;
        }
        __syncthreads();
        // J: r = wr@M
        if (tid < 256) {
            int b = tid & 1, e = tid >> 1;
            const float* Mb = s_M + b * 2048;
            float r = 0.f;
            #pragma unroll
            for (int n = 0; n < 16; n++) r += s_w[b*16+n] * Mb[n * 128 + e];
            s_x[(128 + e) * 2 + b] = r;
        }
        __syncthreads();
    }
}

// ======= labels + tail copies =======
__global__ void tail_kernel(const int* __restrict__ targets, float* __restrict__ out)
{
    int idx = blockIdx.x * blockDim.x + threadIdx.x;
    if (idx < 25600) {
        int b = idx / 400, ss = idx % 400;
        int t = ss / 25, j = ss % 25;
        float val = (j < 24) ? (float)targets[(b * 16 + t) * 24 + j]
                             : ((t == 15) ? 152.0f : 151.0f);
        out[3916800 + idx] = val;
        if (ss >= 375) out[4187200 + b * 25 + (ss - 375)] = val;
    }
    if (idx < 244800) {
        int b = idx / 3825, rem = idx % 3825;
        out[3942400 + idx] = out[(b * 400 + 375) * 153 + rem];
    }
}

extern "C" void kernel_launch(void* const* d_in, const int* in_sizes, int n_in,
                              void* d_out, int out_size)
{
    (void)in_sizes; (void)n_in; (void)out_size;
    const int*   codes1 = (const int*)d_in[0];
    const int*   codes2 = (const int*)d_in[1];
    const int*   targets= (const int*)d_in[2];

    EncP P0 { codes1, (const float*)d_in[3], (const float*)d_in[6],  (const float*)d_in[7],
              (const float*)d_in[8],  (const float*)d_in[9],
              (const float*)d_in[10], (const float*)d_in[11] };
    EncP P1 { codes2, (const float*)d_in[4], (const float*)d_in[12], (const float*)d_in[13],
              (const float*)d_in[14], (const float*)d_in[15],
              (const float*)d_in[16], (const float*)d_in[17] };
    DecP D  { targets,
              (const float*)d_in[18], (const float*)d_in[19],
              (const float*)d_in[20], (const float*)d_in[21],
              (const float*)d_in[23],
              (const float*)d_in[24], (const float*)d_in[25],
              (const float*)d_in[26], (const float*)d_in[27],
              (const float*)d_in[29],
              (float*)d_out };

    static bool attr_done = false;
    if (!attr_done) {
        cudaFuncSetAttribute(enc_kernel, cudaFuncAttributeMaxDynamicSharedMemorySize, 230880);
        cudaFuncSetAttribute(dec_kernel, cudaFuncAttributeMaxDynamicSharedMemorySize, 84160);
        attr_done = true;
    }

    prep_kernel<<<259, 256>>>((const float*)d_in[22], (const float*)d_in[28],
                              (const float*)d_in[5], (const float*)d_in[26]);
    enc_kernel<<<128, 512, 230880>>>(P0, P1);
    dec_kernel<<<32, 768, 84160>>>(D);
    tail_kernel<<<(244800 + 255) / 256, 256>>>(targets, (float*)d_out);
}

// round 5
// speedup vs baseline: 3.5136x; 1.3214x over previous
#include <cuda_runtime.h>

// MANN_Attn R4: fused pipelined kernel.
//  CTAs 0..31   : encoder0, NB=2 (batches 2i, 2i+1)
//  CTAs 32..63  : encoder1, NB=2
//  CTAs 64..95  : decoder, NB=2 — spins on per-tile progress flags
// All 96 CTAs co-resident (1 CTA/SM) -> deadlock-free pipeline.

static __device__ float g_o1[16 * 64 * 32 * 64]; // [t][b][l][e]
static __device__ float g_o2[16 * 64 * 32 * 64];
static __device__ __align__(16) float g_wi_pad[128 * 516];
static __device__ __align__(16) float g_outw_pad[256 * 156];
static __device__ __align__(16) float g_tbl[153 * 128];      // emb2 @ comb_w[0:64]
static __device__ int g_prog[64];                             // tiles done per enc CTA

__device__ __forceinline__ float sigf(float x) { return 1.0f / (1.0f + expf(-x)); }
__device__ __forceinline__ float softplusf(float x) { return (x > 15.0f) ? x : log1pf(expf(x)); }

__global__ void prep_kernel(const float* __restrict__ wi, const float* __restrict__ outw,
                            const float* __restrict__ emb2, const float* __restrict__ combw)
{
    int i = blockIdx.x * 256 + threadIdx.x;
    if (i < 64) g_prog[i] = 0;
    if (i < 128 * 516) { int k = i / 516, j = i % 516; g_wi_pad[i] = (j < 515) ? wi[k * 515 + j] : 0.f; }
    if (i < 256 * 156) { int k = i / 156, j = i % 156; g_outw_pad[i] = (j < 153) ? outw[k * 153 + j] : 0.f; }
    if (i < 153 * 128) {
        int t = i / 128, j = i % 128;
        float a = 0.f;
        #pragma unroll 8
        for (int e = 0; e < 64; e++) a += emb2[t * 64 + e] * combw[e * 128 + j];
        g_tbl[i] = a;
    }
}

struct EncP {
    const int* codes; const float* emb;
    const float *wx, *wh, *bx, *bh, *wi, *bi;
};
struct DecP {
    const int* targets;
    const float *wx, *wh, *bx, *bh, *bi;
    const float *attn0, *attn1, *combw, *combb, *outb;
    float* out;
};

// ---------------- Encoder body (NB=2, wx from L2) ----------------
__device__ void enc_body(const EncP& p, float* o_out, int b0, float* sm)
{
    const int tid = threadIdx.x;
    float* s_wh = sm;               // 12288 (64x192)
    float* s_wi = s_wh + 12288;     // 16640 (64x260 padded)
    float* s_bx = s_wi + 16640;     // 192
    float* s_bh = s_bx + 192;       // 192
    float* s_bi = s_bh + 192;       // 260
    float* s_p  = s_bi + 260;       // 7680 partial union
    float* s_x  = s_p + 7680;       // 256 [k(128)][b]  (x|r)
    float* s_h  = s_x + 256;        // 128 [j][b]
    float* s_gx = s_h + 128;        // 384
    float* s_gh = s_gx + 384;       // 384
    float* s_if = s_gh + 384;       // 520
    float* s_M  = s_if + 520;       // 2048 [b][n][e]
    float* s_mn = s_M + 2048;       // 32
    float* s_md = s_mn + 32;        // 32
    float* s_w  = s_md + 32;        // 32
    float* s_kn = s_w + 32;         // 8

    float* p_gx = s_p;              // 16 x 384
    float* p_gh = s_p + 6144;       // 4 x 384
    float* p_if = s_p;              // 8 x 520 (reuse)

    for (int i = tid; i < 12288; i += 768) s_wh[i] = p.wh[i];
    for (int i = tid; i < 16640; i += 768) {
        int k = i / 260, j = i % 260;
        s_wi[i] = (j < 259) ? p.wi[k * 259 + j] : 0.f;
    }
    if (tid < 192) { s_bx[tid] = p.bx[tid]; s_bh[tid] = p.bh[tid]; }
    if (tid < 260) s_bi[tid] = (tid < 259) ? p.bi[tid] : 0.f;
    if (tid < 256) s_x[tid] = 0.f;
    if (tid < 128) s_h[tid] = 0.f;
    for (int i = tid; i < 2048; i += 768) s_M[i] = 0.f;
    __syncthreads();

    const int c8 = tid & 7;
    const int pq = tid >> 3;        // <32 for tid<256: b*16+n
    const int pb = pq >> 4;
    float* Mp = s_M + pq * 64 + c8 * 8;

    for (int s = 0; s < 512; ++s) {
        // A: x load + gh partials (h_prev)
        if (tid < 128) {
            int b = tid & 1, e = tid >> 1;
            int code = p.codes[(b0 + b) * 512 + s];
            s_x[e * 2 + b] = p.emb[code * 64 + e];
        } else if (tid < 320) {
            int u = tid - 128;
            int jq = u % 48, kh = u / 48;     // 4 ksplits x 16 k
            float a[4][2] = {};
            const float* wb = s_wh + kh * 16 * 192 + jq * 4;
            const float* hb = s_h + kh * 32;
            #pragma unroll
            for (int i = 0; i < 16; i++) {
                float4 w = *(const float4*)(wb + i * 192);
                float2 h = *(const float2*)(hb + 2 * i);
                a[0][0] += w.x * h.x; a[0][1] += w.x * h.y;
                a[1][0] += w.y * h.x; a[1][1] += w.y * h.y;
                a[2][0] += w.z * h.x; a[2][1] += w.z * h.y;
                a[3][0] += w.w * h.x; a[3][1] += w.w * h.y;
            }
            float* d = p_gh + kh * 384 + jq * 8;
            *(float4*)(d)     = make_float4(a[0][0], a[0][1], a[1][0], a[1][1]);
            *(float4*)(d + 4) = make_float4(a[2][0], a[2][1], a[3][0], a[3][1]);
        }
        __syncthreads();
        // B: gx partials, wx from L2: 16 ksplits x 48 jq, 8 iters
        {
            int jq = tid % 48, kq = tid / 48;
            float a[4][2] = {};
            const float* wb = p.wx + kq * 8 * 192 + jq * 4;
            const float* xb = s_x + kq * 16;
            #pragma unroll
            for (int i = 0; i < 8; i++) {
                float4 w = __ldg((const float4*)(wb + i * 192));
                float2 x = *(const float2*)(xb + 2 * i);
                a[0][0] += w.x * x.x; a[0][1] += w.x * x.y;
                a[1][0] += w.y * x.x; a[1][1] += w.y * x.y;
                a[2][0] += w.z * x.x; a[2][1] += w.z * x.y;
                a[3][0] += w.w * x.x; a[3][1] += w.w * x.y;
            }
            float* d = p_gx + kq * 384 + jq * 8;
            *(float4*)(d)     = make_float4(a[0][0], a[0][1], a[1][0], a[1][1]);
            *(float4*)(d + 4) = make_float4(a[2][0], a[2][1], a[3][0], a[3][1]);
        }
        __syncthreads();
        // C: reduce gx (384) + gh (384)
        if (tid < 384) {
            float a = s_bx[tid >> 1];
            #pragma unroll
            for (int kq = 0; kq < 16; kq++) a += p_gx[kq * 384 + tid];
            s_gx[tid] = a;
        } else {
            int u = tid - 384;
            float g = s_bh[u >> 1];
            #pragma unroll
            for (int kh = 0; kh < 4; kh++) g += p_gh[kh * 384 + u];
            s_gh[u] = g;
        }
        __syncthreads();
        // GRU
        if (tid < 128) {
            int b = tid & 1, j = tid >> 1;
            float xr = s_gx[j*2+b], xz = s_gx[(64+j)*2+b], xn = s_gx[(128+j)*2+b];
            float hr = s_gh[j*2+b], hz = s_gh[(64+j)*2+b], hn = s_gh[(128+j)*2+b];
            float rg = sigf(xr + hr), z = sigf(xz + hz);
            float n = tanhf(xn + rg * hn);
            s_h[j*2+b] = (1.0f - z) * n + z * s_h[j*2+b];
        }
        __syncthreads();
        // iface partials: 8 ksplits x 65 jq, 8 iters
        if (tid < 520) {
            int jq = tid % 65, kq = tid / 65;
            float a[4][2] = {};
            const float* wb = s_wi + kq * 8 * 260 + jq * 4;
            const float* hb = s_h + kq * 16;
            #pragma unroll
            for (int i = 0; i < 8; i++) {
                float4 w = *(const float4*)(wb + i * 260);
                float2 h = *(const float2*)(hb + 2 * i);
                a[0][0] += w.x * h.x; a[0][1] += w.x * h.y;
                a[1][0] += w.y * h.x; a[1][1] += w.y * h.y;
                a[2][0] += w.z * h.x; a[2][1] += w.z * h.y;
                a[3][0] += w.w * h.x; a[3][1] += w.w * h.y;
            }
            float* d = p_if + kq * 520 + jq * 8;
            *(float4*)(d)     = make_float4(a[0][0], a[0][1], a[1][0], a[1][1]);
            *(float4*)(d + 4) = make_float4(a[2][0], a[2][1], a[3][0], a[3][1]);
        }
        __syncthreads();
        if (tid < 520) {
            float a = s_bi[tid >> 1];
            #pragma unroll
            for (int kq = 0; kq < 8; kq++) a += p_if[kq * 520 + tid];
            s_if[tid] = a;
        }
        __syncthreads();
        // M pre-stats + key norms
        if (tid < 256) {
            float ss = 0.f, dw = 0.f;
            #pragma unroll
            for (int i = 0; i < 8; i++) {
                float m = Mp[i];
                ss += m * m; dw += m * s_if[(64 + c8 * 8 + i) * 2 + pb];
            }
            for (int d = 4; d > 0; d >>= 1) {
                ss += __shfl_down_sync(0xffffffffu, ss, d);
                dw += __shfl_down_sync(0xffffffffu, dw, d);
            }
            if (c8 == 0) { s_mn[pq] = sqrtf(ss); s_md[pq] = dw; }
        } else if (tid < 384) {
            int w = (tid >> 5) - 8, lane = tid & 31;  // 4 warps
            int b = w & 1, isr = w >> 1;
            int base = isr ? 0 : 64;
            float v0 = s_if[(base + lane) * 2 + b], v1 = s_if[(base + 32 + lane) * 2 + b];
            float t2 = v0 * v0 + v1 * v1;
            for (int d = 16; d > 0; d >>= 1) t2 += __shfl_down_sync(0xffffffffu, t2, d);
            if (lane == 0) s_kn[isr * 2 + b] = sqrtf(t2);
        }
        __syncthreads();
        // ww softmax (2 half-warps)
        if (tid < 64 && (tid & 31) < 16) {
            int b = tid >> 5, n = tid & 15;
            float bw = softplusf(s_if[257*2+b]) + 1.0f;
            float gw = sigf(s_if[258*2+b]);
            float kn = s_kn[0*2+b];
            float sc = bw * (s_md[b*16+n] / (s_mn[b*16+n] * kn + 1e-6f));
            float mx = sc;
            for (int d = 8; d > 0; d >>= 1) mx = fmaxf(mx, __shfl_xor_sync(0xffffu, mx, d));
            float e = expf(sc - mx);
            float sum = e;
            for (int d = 8; d > 0; d >>= 1) sum += __shfl_xor_sync(0xffffu, sum, d);
            s_w[b*16+n] = e * (gw / sum);
        }
        __syncthreads();
        // M update + post stats
        if (tid < 256) {
            float wwv = s_w[pq], ss = 0.f, dr = 0.f;
            #pragma unroll
            for (int i = 0; i < 8; i++) {
                int e = c8 * 8 + i;
                float er = sigf(s_if[(128 + e) * 2 + pb]);
                float wv = s_if[(192 + e) * 2 + pb];
                float m = Mp[i];
                m = m * (1.0f - wwv * er) + wwv * wv;
                Mp[i] = m;
                ss += m * m; dr += m * s_if[e * 2 + pb];
            }
            for (int d = 4; d > 0; d >>= 1) {
                ss += __shfl_down_sync(0xffffffffu, ss, d);
                dr += __shfl_down_sync(0xffffffffu, dr, d);
            }
            if (c8 == 0) { s_mn[pq] = sqrtf(ss); s_md[pq] = dr; }
        }
        __syncthreads();
        // wr softmax
        if (tid < 64 && (tid & 31) < 16) {
            int b = tid >> 5, n = tid & 15;
            float br = softplusf(s_if[256*2+b]) + 1.0f;
            float kn = s_kn[1*2+b];
            float sc = br * (s_md[b*16+n] / (s_mn[b*16+n] * kn + 1e-6f));
            float mx = sc;
            for (int d = 8; d > 0; d >>= 1) mx = fmaxf(mx, __shfl_xor_sync(0xffffu, mx, d));
            float e = expf(sc - mx);
            float sum = e;
            for (int d = 8; d > 0; d >>= 1) sum += __shfl_xor_sync(0xffffu, sum, d);
            s_w[b*16+n] = e / sum;
        }
        __syncthreads();
        // r = wr@M ; emit h
        if (tid < 128) {
            int b = tid & 1, e = tid >> 1;
            const float* Mb = s_M + b * 1024;
            float r = 0.f;
            #pragma unroll
            for (int n = 0; n < 16; n++) r += s_w[b*16+n] * Mb[n * 64 + e];
            s_x[(64 + e) * 2 + b] = r;
            o_out[(((s >> 5) * 64 + (b0 + b)) * 32 + (s & 31)) * 64 + e] = s_h[e * 2 + b];
        }
        __syncthreads();
        if ((s & 31) == 31) {          // tile complete -> release flag
            __threadfence();
            if (tid == 0) atomicExch(&g_prog[blockIdx.x], (s >> 5) + 1);
        }
    }
}

// ---------------- Decoder body (NB=2) ----------------
__device__ void dec_body(const DecP& p, int jj, float* sm)
{
    const int b0 = jj * 2;
    const int tid = threadIdx.x;

    float* s_p  = sm;            // 12288 partial union
    float* s_x  = s_p + 12288;   // 512
    float* s_h  = s_x + 512;     // 256
    float* s_gx = s_h + 256;     // 768
    float* s_gh = s_gx + 768;    // 768
    float* s_if = s_gh + 768;    // 1032
    float* s_M  = s_if + 1032;   // 4096
    float* s_c  = s_M + 4096;    // 256
    float* s_cc = s_c + 256;     // 256
    float* s_oc = s_cc + 256;    // 312
    float* s_at = s_oc + 312;    // 128
    float* s_mn = s_at + 128;    // 32
    float* s_md = s_mn + 32;     // 32
    float* s_w  = s_md + 32;     // 32
    float* s_kn = s_w + 32;      // 8

    float* p_wx = s_p;           // 8 x 768
    float* p_wh = s_p + 6144;    // 4 x 768
    float* p_if = s_p;           // 4 x 1032
    float* p_oh = s_p + 4224;    // 4 x 312
    float* p_cb = s_p;           // 4 x 256 (per-v)
    float* p_oc = s_p + 1024;    // 4 x 312 (per-v)

    for (int i = tid; i < 512; i += 768) s_x[i] = 0.f;
    for (int i = tid; i < 4096; i += 768) s_M[i] = 0.f;
    __syncthreads();

    // wait for encoder tile 0 (h_dec0 = hs[31])
    if (tid == 0) {
        while (*(volatile int*)&g_prog[jj] < 1 || *(volatile int*)&g_prog[32 + jj] < 1)
            __nanosleep(200);
    }
    __syncthreads();
    if (tid < 256) {
        int b = tid & 1, e = tid >> 1;
        float h = (e < 64) ? g_o1[((b0 + b) * 32 + 31) * 64 + e]
                           : g_o2[((b0 + b) * 32 + 31) * 64 + (e - 64)];
        s_h[e * 2 + b] = h;
    }
    __syncthreads();

    const int c8 = tid & 7;
    const int pq = tid >> 3;
    const int pb = pq >> 4;
    float* Mp = s_M + pq * 128 + c8 * 16;

    for (int s = 0; s < 400; ++s) {
        const int v = s / 25, pos = s - v * 25;

        if (pos == 0) {
            if (tid == 0) {          // wait for encoder tile v
                while (*(volatile int*)&g_prog[jj] <= v || *(volatile int*)&g_prog[32 + jj] <= v)
                    __nanosleep(200);
            }
            __syncthreads();
            // V0: attention scores
            if (tid < 256) {
                int cc = tid & 1, g = tid >> 1;
                int a = g >> 6, b = (g >> 5) & 1, l = g & 31;
                const float* op = (a ? g_o2 : g_o1) + ((v * 64 + (b0 + b)) * 32 + l) * 64 + cc * 32;
                const float* aw = (a ? p.attn1 : p.attn0) + 128 + cc * 32;
                float sc = 0.f;
                #pragma unroll
                for (int e = 0; e < 32; e++) sc += op[e] * __ldg(aw + e);
                sc += __shfl_down_sync(0xffffffffu, sc, 1);
                if (cc == 0) s_at[g] = sc;
            }
            __syncthreads();
            // V1: softmax
            if (tid < 128) {
                int w = tid >> 5, l = tid & 31;
                float vsc = s_at[w * 32 + l];
                float mx = vsc;
                for (int d = 16; d > 0; d >>= 1) mx = fmaxf(mx, __shfl_xor_sync(0xffffffffu, mx, d));
                float e2 = expf(vsc - mx);
                float sum = e2;
                for (int d = 16; d > 0; d >>= 1) sum += __shfl_xor_sync(0xffffffffu, sum, d);
                s_at[w * 32 + l] = e2 / sum;
            }
            __syncthreads();
            // V2: contexts
            if (tid < 256) {
                int a = tid >> 7, b = (tid >> 6) & 1, e = tid & 63;
                const float* op = (a ? g_o2 : g_o1) + ((v * 64 + (b0 + b)) * 32) * 64 + e;
                const float* at = s_at + a * 64 + b * 32;
                float cv = 0.f;
                #pragma unroll
                for (int l = 0; l < 32; l++) cv += at[l] * op[l * 64];
                s_c[(a * 64 + e) * 2 + b] = cv;
            }
            __syncthreads();
            // V3: comb_cc + out_cc partials
            if (tid < 128) {
                int jq = tid & 31, kq = tid >> 5;
                float a[4][2] = {};
                const float* wb = p.combw + (64 + kq * 32) * 128 + jq * 4;
                const float* xb = s_c + kq * 64;
                #pragma unroll
                for (int i = 0; i < 32; i++) {
                    float4 w = __ldg((const float4*)(wb + i * 128));
                    float2 x = *(const float2*)(xb + 2 * i);
                    a[0][0] += w.x * x.x; a[0][1] += w.x * x.y;
                    a[1][0] += w.y * x.x; a[1][1] += w.y * x.y;
                    a[2][0] += w.z * x.x; a[2][1] += w.z * x.y;
                    a[3][0] += w.w * x.x; a[3][1] += w.w * x.y;
                }
                float* d = p_cb + kq * 256 + jq * 8;
                *(float4*)(d)     = make_float4(a[0][0], a[0][1], a[1][0], a[1][1]);
                *(float4*)(d + 4) = make_float4(a[2][0], a[2][1], a[3][0], a[3][1]);
            } else if (tid < 284) {
                int u = tid - 128;
                int jq = u % 39, kq = u / 39;
                float a[4][2] = {};
                const float* wb = g_outw_pad + (128 + kq * 32) * 156 + jq * 4;
                const float* xb = s_c + kq * 64;
                #pragma unroll
                for (int i = 0; i < 32; i++) {
                    float4 w = *(const float4*)(wb + i * 156);
                    float2 x = *(const float2*)(xb + 2 * i);
                    a[0][0] += w.x * x.x; a[0][1] += w.x * x.y;
                    a[1][0] += w.y * x.x; a[1][1] += w.y * x.y;
                    a[2][0] += w.z * x.x; a[2][1] += w.z * x.y;
                    a[3][0] += w.w * x.x; a[3][1] += w.w * x.y;
                }
                float* d = p_oc + kq * 312 + jq * 8;
                *(float4*)(d)     = make_float4(a[0][0], a[0][1], a[1][0], a[1][1]);
                *(float4*)(d + 4) = make_float4(a[2][0], a[2][1], a[3][0], a[3][1]);
            }
            __syncthreads();
            // V4: reduce
            if (tid < 256) {
                float a = __ldg(p.combb + (tid >> 1));
                #pragma unroll
                for (int kq = 0; kq < 4; kq++) a += p_cb[kq * 256 + tid];
                s_cc[tid] = a;
            } else if (tid < 568) {
                int idx = tid - 256;
                int j = idx >> 1;
                float a = (j < 153) ? __ldg(p.outb + j) : 0.f;
                #pragma unroll
                for (int kq = 0; kq < 4; kq++) a += p_oc[kq * 312 + idx];
                s_oc[idx] = a;
            }
            __syncthreads();
        }

        // A: comb via token table + wh partials
        if (tid < 256) {
            int b = tid & 1, j = tid >> 1;
            int tok = (pos == 0) ? ((v == 0) ? 150 : 151)
                                 : p.targets[((b0 + b) * 16 + v) * 24 + (pos - 1)];
            s_x[tid] = fmaxf(__ldg(g_tbl + tok * 128 + j) + s_cc[tid], 0.f);
        } else if (tid < 640) {
            int u = tid - 256;
            int jq = u % 96, kq = u / 96;
            float g[4][2] = {};
            const float* wb = p.wh + kq * 32 * 384 + jq * 4;
            const float* hb = s_h + kq * 64;
            #pragma unroll
            for (int i = 0; i < 32; i++) {
                float4 w = __ldg((const float4*)(wb + i * 384));
                float2 h = *(const float2*)(hb + 2 * i);
                g[0][0] += w.x * h.x; g[0][1] += w.x * h.y;
                g[1][0] += w.y * h.x; g[1][1] += w.y * h.y;
                g[2][0] += w.z * h.x; g[2][1] += w.z * h.y;
                g[3][0] += w.w * h.x; g[3][1] += w.w * h.y;
            }
            float* d2 = p_wh + kq * 768 + jq * 8;
            *(float4*)(d2)     = make_float4(g[0][0], g[0][1], g[1][0], g[1][1]);
            *(float4*)(d2 + 4) = make_float4(g[2][0], g[2][1], g[3][0], g[3][1]);
        }
        __syncthreads();
        // B: wx partials
        {
            int jq = tid % 96, kq = tid / 96;
            float a[4][2] = {};
            const float* wb = p.wx + kq * 32 * 384 + jq * 4;
            const float* xb = s_x + kq * 64;
            #pragma unroll
            for (int i = 0; i < 32; i++) {
                float4 w = __ldg((const float4*)(wb + i * 384));
                float2 x = *(const float2*)(xb + 2 * i);
                a[0][0] += w.x * x.x; a[0][1] += w.x * x.y;
                a[1][0] += w.y * x.x; a[1][1] += w.y * x.y;
                a[2][0] += w.z * x.x; a[2][1] += w.z * x.y;
                a[3][0] += w.w * x.x; a[3][1] += w.w * x.y;
            }
            float* d = p_wx + kq * 768 + jq * 8;
            *(float4*)(d)     = make_float4(a[0][0], a[0][1], a[1][0], a[1][1]);
            *(float4*)(d + 4) = make_float4(a[2][0], a[2][1], a[3][0], a[3][1]);
        }
        __syncthreads();
        // C1: reduce gx/gh
        {
            float a = __ldg(p.bx + (tid >> 1));
            float g = __ldg(p.bh + (tid >> 1));
            #pragma unroll
            for (int kq = 0; kq < 8; kq++) a += p_wx[kq * 768 + tid];
            #pragma unroll
            for (int kq = 0; kq < 4; kq++) g += p_wh[kq * 768 + tid];
            s_gx[tid] = a; s_gh[tid] = g;
        }
        __syncthreads();
        // C2: GRU
        if (tid < 256) {
            int b = tid & 1, j = tid >> 1;
            float xr = s_gx[j*2+b], xz = s_gx[(128+j)*2+b], xn = s_gx[(256+j)*2+b];
            float hr = s_gh[j*2+b], hz = s_gh[(128+j)*2+b], hn = s_gh[(256+j)*2+b];
            float rg = sigf(xr + hr), z = sigf(xz + hz);
            float n = tanhf(xn + rg * hn);
            s_h[j*2+b] = (1.0f - z) * n + z * s_h[j*2+b];
        }
        __syncthreads();
        // D: wi + outw(h2) partials
        if (tid < 516) {
            int jq = tid % 129, kq = tid / 129;
            float a[4][2] = {};
            const float* wb = g_wi_pad + kq * 32 * 516 + jq * 4;
            const float* hb = s_h + kq * 64;
            #pragma unroll
            for (int i = 0; i < 32; i++) {
                float4 w = *(const float4*)(wb + i * 516);
                float2 h = *(const float2*)(hb + 2 * i);
                a[0][0] += w.x * h.x; a[0][1] += w.x * h.y;
                a[1][0] += w.y * h.x; a[1][1] += w.y * h.y;
                a[2][0] += w.z * h.x; a[2][1] += w.z * h.y;
                a[3][0] += w.w * h.x; a[3][1] += w.w * h.y;
            }
            float* d = p_if + kq * 1032 + jq * 8;
            *(float4*)(d)     = make_float4(a[0][0], a[0][1], a[1][0], a[1][1]);
            *(float4*)(d + 4) = make_float4(a[2][0], a[2][1], a[3][0], a[3][1]);
        } else if (tid < 672) {
            int u = tid - 516;
            int jq = u % 39, kq = u / 39;
            float a[4][2] = {};
            const float* wb = g_outw_pad + kq * 32 * 156 + jq * 4;
            const float* hb = s_h + kq * 64;
            #pragma unroll
            for (int i = 0; i < 32; i++) {
                float4 w = *(const float4*)(wb + i * 156);
                float2 h = *(const float2*)(hb + 2 * i);
                a[0][0] += w.x * h.x; a[0][1] += w.x * h.y;
                a[1][0] += w.y * h.x; a[1][1] += w.y * h.y;
                a[2][0] += w.z * h.x; a[2][1] += w.z * h.y;
                a[3][0] += w.w * h.x; a[3][1] += w.w * h.y;
            }
            float* d = p_oh + kq * 312 + jq * 8;
            *(float4*)(d)     = make_float4(a[0][0], a[0][1], a[1][0], a[1][1]);
            *(float4*)(d + 4) = make_float4(a[2][0], a[2][1], a[3][0], a[3][1]);
        }
        __syncthreads();
        // E: reduce iface + logits store
        for (int u = tid; u < 1030; u += 768) {
            float a = __ldg(p.bi + (u >> 1));
            #pragma unroll
            for (int kq = 0; kq < 4; kq++) a += p_if[kq * 1032 + u];
            s_if[u] = a;
        }
        if (tid < 306) {
            int j = tid >> 1, b = tid & 1;
            float a = s_oc[tid];
            #pragma unroll
            for (int kq = 0; kq < 4; kq++) a += p_oh[kq * 312 + tid];
            p.out[((b0 + b) * 400 + s) * 153 + j] = a;
        }
        __syncthreads();
        // F: M pre-stats + key norms
        if (tid < 256) {
            float ss = 0.f, dw = 0.f;
            #pragma unroll
            for (int i = 0; i < 16; i++) {
                float m = Mp[i];
                ss += m * m; dw += m * s_if[(128 + c8 * 16 + i) * 2 + pb];
            }
            for (int d = 4; d > 0; d >>= 1) {
                ss += __shfl_down_sync(0xffffffffu, ss, d);
                dw += __shfl_down_sync(0xffffffffu, dw, d);
            }
            if (c8 == 0) { s_mn[pq] = sqrtf(ss); s_md[pq] = dw; }
        } else if (tid < 384) {
            int w = (tid >> 5) - 8, lane = tid & 31;
            int b = w & 1, isr = w >> 1;
            int base = isr ? 0 : 128;
            float t2 = 0.f;
            #pragma unroll
            for (int q = 0; q < 4; q++) {
                float vq = s_if[(base + lane + q * 32) * 2 + b];
                t2 += vq * vq;
            }
            for (int d = 16; d > 0; d >>= 1) t2 += __shfl_down_sync(0xffffffffu, t2, d);
            if (lane == 0) s_kn[isr * 2 + b] = sqrtf(t2);
        }
        __syncthreads();
        // G: ww softmax
        if (tid < 64 && (tid & 31) < 16) {
            int b = tid >> 5, n = tid & 15;
            float bw = softplusf(s_if[513*2+b]) + 1.0f;
            float gw = sigf(s_if[514*2+b]);
            float kn = s_kn[0*2+b];
            float sc = bw * (s_md[b*16+n] / (s_mn[b*16+n] * kn + 1e-6f));
            float mx = sc;
            for (int d = 8; d > 0; d >>= 1) mx = fmaxf(mx, __shfl_xor_sync(0xffffu, mx, d));
            float e = expf(sc - mx);
            float sum = e;
            for (int d = 8; d > 0; d >>= 1) sum += __shfl_xor_sync(0xffffu, sum, d);
            s_w[b*16+n] = e * (gw / sum);
        }
        __syncthreads();
        // H: M update + post stats
        if (tid < 256) {
            float wwv = s_w[pq], ss = 0.f, dr = 0.f;
            #pragma unroll
            for (int i = 0; i < 16; i++) {
                int e = c8 * 16 + i;
                float er = sigf(s_if[(256 + e) * 2 + pb]);
                float wv = s_if[(384 + e) * 2 + pb];
                float m = Mp[i];
                m = m * (1.0f - wwv * er) + wwv * wv;
                Mp[i] = m;
                ss += m * m; dr += m * s_if[e * 2 + pb];
            }
            for (int d = 4; d > 0; d >>= 1) {
                ss += __shfl_down_sync(0xffffffffu, ss, d);
                dr += __shfl_down_sync(0xffffffffu, dr, d);
            }
            if (c8 == 0) { s_mn[pq] = sqrtf(ss); s_md[pq] = dr; }
        }
        __syncthreads();
        // I: wr softmax
        if (tid < 64 && (tid & 31) < 16) {
            int b = tid >> 5, n = tid & 15;
            float br = softplusf(s_if[512*2+b]) + 1.0f;
            float kn = s_kn[1*2+b];
            float sc = br * (s_md[b*16+n] / (s_mn[b*16+n] * kn + 1e-6f));
            float mx = sc;
            for (int d = 8; d > 0; d >>= 1) mx = fmaxf(mx, __shfl_xor_sync(0xffffu, mx, d));
            float e = expf(sc - mx);
            float sum = e;
            for (int d = 8; d > 0; d >>= 1) sum += __shfl_xor_sync(0xffffu, sum, d);
            s_w[b*16+n] = e / sum;
        }
        __syncthreads();
        // J: r = wr@M
        if (tid < 256) {
            int b = tid & 1, e = tid >> 1;
            const float* Mb = s_M + b * 2048;
            float r = 0.f;
            #pragma unroll
            for (int n = 0; n < 16; n++) r += s_w[b*16+n] * Mb[n * 128 + e];
            s_x[(128 + e) * 2 + b] = r;
        }
        __syncthreads();
    }
}

__global__ void __launch_bounds__(768, 1)
fused_kernel(EncP P0, EncP P1, DecP D)
{
    extern __shared__ float sm[];
    int bid = blockIdx.x;
    if (bid < 64) {
        const EncP& p = (bid < 32) ? P0 : P1;
        float* o_out = (bid < 32) ? g_o1 : g_o2;
        enc_body(p, o_out, (bid & 31) * 2, sm);
    } else {
        dec_body(D, bid - 64, sm);
    }
}

// ======= labels + tail copies =======
__global__ void tail_kernel(const int* __restrict__ targets, float* __restrict__ out)
{
    int idx = blockIdx.x * blockDim.x + threadIdx.x;
    if (idx < 25600) {
        int b = idx / 400, ss = idx % 400;
        int t = ss / 25, j = ss % 25;
        float val = (j < 24) ? (float)targets[(b * 16 + t) * 24 + j]
                             : ((t == 15) ? 152.0f : 151.0f);
        out[3916800 + idx] = val;
        if (ss >= 375) out[4187200 + b * 25 + (ss - 375)] = val;
    }
    if (idx < 244800) {
        int b = idx / 3825, rem = idx % 3825;
        out[3942400 + idx] = out[(b * 400 + 375) * 153 + rem];
    }
}

extern "C" void kernel_launch(void* const* d_in, const int* in_sizes, int n_in,
                              void* d_out, int out_size)
{
    (void)in_sizes; (void)n_in; (void)out_size;
    const int*   codes1 = (const int*)d_in[0];
    const int*   codes2 = (const int*)d_in[1];
    const int*   targets= (const int*)d_in[2];

    EncP P0 { codes1, (const float*)d_in[3], (const float*)d_in[6],  (const float*)d_in[7],
              (const float*)d_in[8],  (const float*)d_in[9],
              (const float*)d_in[10], (const float*)d_in[11] };
    EncP P1 { codes2, (const float*)d_in[4], (const float*)d_in[12], (const float*)d_in[13],
              (const float*)d_in[14], (const float*)d_in[15],
              (const float*)d_in[16], (const float*)d_in[17] };
    DecP D  { targets,
              (const float*)d_in[18], (const float*)d_in[19],
              (const float*)d_in[20], (const float*)d_in[21],
              (const float*)d_in[23],
              (const float*)d_in[24], (const float*)d_in[25],
              (const float*)d_in[26], (const float*)d_in[27],
              (const float*)d_in[29],
              (float*)d_out };

    static bool attr_done = false;
    if (!attr_done) {
        cudaFuncSetAttribute(fused_kernel, cudaFuncAttributeMaxDynamicSharedMemorySize, 164320);
        attr_done = true;
    }

    prep_kernel<<<259, 256>>>((const float*)d_in[22], (const float*)d_in[28],
                              (const float*)d_in[5], (const float*)d_in[26]);
    fused_kernel<<<96, 768, 164320>>>(P0, P1, D);
    tail_kernel<<<(244800 + 255) / 256, 256>>>(targets, (float*)d_out);
}

// round 6
// speedup vs baseline: 3.5696x; 1.0159x over previous
#include <cuda_runtime.h>

// MANN_Attn R5: fused pipelined kernel + packed f32x2 FFMA2 GEMVs.
//  CTAs 0..31   : encoder0, NB=2 ; CTAs 32..63 : encoder1, NB=2
//  CTAs 64..95  : decoder, NB=2 — spins on per-tile progress flags

typedef unsigned long long u64;

static __device__ float g_o1[16 * 64 * 32 * 64]; // [t][b][l][e]
static __device__ float g_o2[16 * 64 * 32 * 64];
static __device__ __align__(16) float g_wi_pad[128 * 516];
static __device__ __align__(16) float g_outw_pad[256 * 156];
static __device__ __align__(16) float g_tbl[153 * 128];      // emb2 @ comb_w[0:64]
static __device__ int g_prog[64];

__device__ __forceinline__ float sigf(float x) { return 1.0f / (1.0f + expf(-x)); }
__device__ __forceinline__ float softplusf(float x) { return (x > 15.0f) ? x : log1pf(expf(x)); }
__device__ __forceinline__ u64 bc2(float w) {
    u64 r; asm("mov.b64 %0, {%1, %1};" : "=l"(r) : "f"(w)); return r;
}
__device__ __forceinline__ void fma2(u64& a, u64 w, u64 x) {
    asm("fma.rn.f32x2 %0, %1, %2, %0;" : "+l"(a) : "l"(w), "l"(x));
}

__global__ void prep_kernel(const float* __restrict__ wi, const float* __restrict__ outw,
                            const float* __restrict__ emb2, const float* __restrict__ combw)
{
    int i = blockIdx.x * 256 + threadIdx.x;
    if (i < 64) g_prog[i] = 0;
    if (i < 128 * 516) { int k = i / 516, j = i % 516; g_wi_pad[i] = (j < 515) ? wi[k * 515 + j] : 0.f; }
    if (i < 256 * 156) { int k = i / 156, j = i % 156; g_outw_pad[i] = (j < 153) ? outw[k * 153 + j] : 0.f; }
    if (i < 153 * 128) {
        int t = i / 128, j = i % 128;
        float a = 0.f;
        #pragma unroll 8
        for (int e = 0; e < 64; e++) a += emb2[t * 64 + e] * combw[e * 128 + j];
        g_tbl[i] = a;
    }
}

struct EncP {
    const int* codes; const float* emb;
    const float *wx, *wh, *bx, *bh, *wi, *bi;
};
struct DecP {
    const int* targets;
    const float *wx, *wh, *bx, *bh, *bi;
    const float *attn0, *attn1, *combw, *combb, *outb;
    float* out;
};

// ---------------- Encoder body (NB=2, wx from L2) ----------------
__device__ void enc_body(const EncP& p, float* o_out, int b0, float* sm)
{
    const int tid = threadIdx.x;
    float* s_wh = sm;               // 12288 (64x192)
    float* s_wi = s_wh + 12288;     // 16640 (64x260 padded)
    float* s_bx = s_wi + 16640;     // 192
    float* s_bh = s_bx + 192;       // 192
    float* s_bi = s_bh + 192;       // 260
    float* s_p  = s_bi + 260;       // 7680 partial union
    float* s_x  = s_p + 7680;       // 256 [k(128)][b]  (x|r)
    float* s_h  = s_x + 256;        // 128 [j][b]
    float* s_gx = s_h + 128;        // 384
    float* s_gh = s_gx + 384;       // 384
    float* s_if = s_gh + 384;       // 520
    float* s_M  = s_if + 520;       // 2048 [b][n][e]
    float* s_mn = s_M + 2048;       // 32
    float* s_md = s_mn + 32;        // 32
    float* s_w  = s_md + 32;        // 32
    float* s_kn = s_w + 32;         // 8

    float* p_gx = s_p;              // 16 x 384
    float* p_gh = s_p + 6144;       // 4 x 384
    float* p_if = s_p;              // 8 x 520 (reuse)

    for (int i = tid; i < 12288; i += 768) s_wh[i] = p.wh[i];
    for (int i = tid; i < 16640; i += 768) {
        int k = i / 260, j = i % 260;
        s_wi[i] = (j < 259) ? p.wi[k * 259 + j] : 0.f;
    }
    if (tid < 192) { s_bx[tid] = p.bx[tid]; s_bh[tid] = p.bh[tid]; }
    if (tid < 260) s_bi[tid] = (tid < 259) ? p.bi[tid] : 0.f;
    if (tid < 256) s_x[tid] = 0.f;
    if (tid < 128) s_h[tid] = 0.f;
    for (int i = tid; i < 2048; i += 768) s_M[i] = 0.f;
    __syncthreads();

    const int c8 = tid & 7;
    const int pq = tid >> 3;
    const int pb = pq >> 4;
    float* Mp = s_M + pq * 64 + c8 * 8;

    for (int s = 0; s < 512; ++s) {
        // A: x load + gh partials (h_prev)
        if (tid < 128) {
            int b = tid & 1, e = tid >> 1;
            int code = p.codes[(b0 + b) * 512 + s];
            s_x[e * 2 + b] = p.emb[code * 64 + e];
        } else if (tid < 320) {
            int u = tid - 128;
            int jq = u % 48, kh = u / 48;     // 4 ksplits x 16 k
            u64 a0 = 0, a1 = 0, a2 = 0, a3 = 0;
            const float* wb = s_wh + kh * 16 * 192 + jq * 4;
            const u64* xb = (const u64*)(s_h + kh * 32);
            #pragma unroll
            for (int i = 0; i < 16; i++) {
                float4 w = *(const float4*)(wb + i * 192);
                u64 x2 = xb[i];
                fma2(a0, bc2(w.x), x2); fma2(a1, bc2(w.y), x2);
                fma2(a2, bc2(w.z), x2); fma2(a3, bc2(w.w), x2);
            }
            u64* d = (u64*)(p_gh + kh * 384 + jq * 8);
            d[0] = a0; d[1] = a1; d[2] = a2; d[3] = a3;
        }
        __syncthreads();
        // B: gx partials, wx from L2: 16 ksplits x 48 jq, 8 iters
        {
            int jq = tid % 48, kq = tid / 48;
            u64 a0 = 0, a1 = 0, a2 = 0, a3 = 0;
            const float* wb = p.wx + kq * 8 * 192 + jq * 4;
            const u64* xb = (const u64*)(s_x + kq * 16);
            #pragma unroll
            for (int i = 0; i < 8; i++) {
                float4 w = __ldg((const float4*)(wb + i * 192));
                u64 x2 = xb[i];
                fma2(a0, bc2(w.x), x2); fma2(a1, bc2(w.y), x2);
                fma2(a2, bc2(w.z), x2); fma2(a3, bc2(w.w), x2);
            }
            u64* d = (u64*)(p_gx + kq * 384 + jq * 8);
            d[0] = a0; d[1] = a1; d[2] = a2; d[3] = a3;
        }
        __syncthreads();
        // C: reduce gx (384) + gh (384)
        if (tid < 384) {
            float a = s_bx[tid >> 1];
            #pragma unroll
            for (int kq = 0; kq < 16; kq++) a += p_gx[kq * 384 + tid];
            s_gx[tid] = a;
        } else {
            int u = tid - 384;
            float g = s_bh[u >> 1];
            #pragma unroll
            for (int kh = 0; kh < 4; kh++) g += p_gh[kh * 384 + u];
            s_gh[u] = g;
        }
        __syncthreads();
        // GRU
        if (tid < 128) {
            int b = tid & 1, j = tid >> 1;
            float xr = s_gx[j*2+b], xz = s_gx[(64+j)*2+b], xn = s_gx[(128+j)*2+b];
            float hr = s_gh[j*2+b], hz = s_gh[(64+j)*2+b], hn = s_gh[(128+j)*2+b];
            float rg = sigf(xr + hr), z = sigf(xz + hz);
            float n = tanhf(xn + rg * hn);
            s_h[j*2+b] = (1.0f - z) * n + z * s_h[j*2+b];
        }
        __syncthreads();
        // iface partials: 8 ksplits x 65 jq, 8 iters
        if (tid < 520) {
            int jq = tid % 65, kq = tid / 65;
            u64 a0 = 0, a1 = 0, a2 = 0, a3 = 0;
            const float* wb = s_wi + kq * 8 * 260 + jq * 4;
            const u64* xb = (const u64*)(s_h + kq * 16);
            #pragma unroll
            for (int i = 0; i < 8; i++) {
                float4 w = *(const float4*)(wb + i * 260);
                u64 x2 = xb[i];
                fma2(a0, bc2(w.x), x2); fma2(a1, bc2(w.y), x2);
                fma2(a2, bc2(w.z), x2); fma2(a3, bc2(w.w), x2);
            }
            u64* d = (u64*)(p_if + kq * 520 + jq * 8);
            d[0] = a0; d[1] = a1; d[2] = a2; d[3] = a3;
        }
        __syncthreads();
        if (tid < 520) {
            float a = s_bi[tid >> 1];
            #pragma unroll
            for (int kq = 0; kq < 8; kq++) a += p_if[kq * 520 + tid];
            s_if[tid] = a;
        }
        __syncthreads();
        // M pre-stats + key norms
        if (tid < 256) {
            float ss = 0.f, dw = 0.f;
            #pragma unroll
            for (int i = 0; i < 8; i++) {
                float m = Mp[i];
                ss += m * m; dw += m * s_if[(64 + c8 * 8 + i) * 2 + pb];
            }
            for (int d = 4; d > 0; d >>= 1) {
                ss += __shfl_down_sync(0xffffffffu, ss, d);
                dw += __shfl_down_sync(0xffffffffu, dw, d);
            }
            if (c8 == 0) { s_mn[pq] = sqrtf(ss); s_md[pq] = dw; }
        } else if (tid < 384) {
            int w = (tid >> 5) - 8, lane = tid & 31;
            int b = w & 1, isr = w >> 1;
            int base = isr ? 0 : 64;
            float v0 = s_if[(base + lane) * 2 + b], v1 = s_if[(base + 32 + lane) * 2 + b];
            float t2 = v0 * v0 + v1 * v1;
            for (int d = 16; d > 0; d >>= 1) t2 += __shfl_down_sync(0xffffffffu, t2, d);
            if (lane == 0) s_kn[isr * 2 + b] = sqrtf(t2);
        }
        __syncthreads();
        // ww softmax
        if (tid < 64 && (tid & 31) < 16) {
            int b = tid >> 5, n = tid & 15;
            float bw = softplusf(s_if[257*2+b]) + 1.0f;
            float gw = sigf(s_if[258*2+b]);
            float kn = s_kn[0*2+b];
            float sc = bw * (s_md[b*16+n] / (s_mn[b*16+n] * kn + 1e-6f));
            float mx = sc;
            for (int d = 8; d > 0; d >>= 1) mx = fmaxf(mx, __shfl_xor_sync(0xffffu, mx, d));
            float e = expf(sc - mx);
            float sum = e;
            for (int d = 8; d > 0; d >>= 1) sum += __shfl_xor_sync(0xffffu, sum, d);
            s_w[b*16+n] = e * (gw / sum);
        }
        __syncthreads();
        // M update + post stats
        if (tid < 256) {
            float wwv = s_w[pq], ss = 0.f, dr = 0.f;
            #pragma unroll
            for (int i = 0; i < 8; i++) {
                int e = c8 * 8 + i;
                float er = sigf(s_if[(128 + e) * 2 + pb]);
                float wv = s_if[(192 + e) * 2 + pb];
                float m = Mp[i];
                m = m * (1.0f - wwv * er) + wwv * wv;
                Mp[i] = m;
                ss += m * m; dr += m * s_if[e * 2 + pb];
            }
            for (int d = 4; d > 0; d >>= 1) {
                ss += __shfl_down_sync(0xffffffffu, ss, d);
                dr += __shfl_down_sync(0xffffffffu, dr, d);
            }
            if (c8 == 0) { s_mn[pq] = sqrtf(ss); s_md[pq] = dr; }
        }
        __syncthreads();
        // wr softmax
        if (tid < 64 && (tid & 31) < 16) {
            int b = tid >> 5, n = tid & 15;
            float br = softplusf(s_if[256*2+b]) + 1.0f;
            float kn = s_kn[1*2+b];
            float sc = br * (s_md[b*16+n] / (s_mn[b*16+n] * kn + 1e-6f));
            float mx = sc;
            for (int d = 8; d > 0; d >>= 1) mx = fmaxf(mx, __shfl_xor_sync(0xffffu, mx, d));
            float e = expf(sc - mx);
            float sum = e;
            for (int d = 8; d > 0; d >>= 1) sum += __shfl_xor_sync(0xffffu, sum, d);
            s_w[b*16+n] = e / sum;
        }
        __syncthreads();
        // r = wr@M ; emit h
        if (tid < 128) {
            int b = tid & 1, e = tid >> 1;
            const float* Mb = s_M + b * 1024;
            float r = 0.f;
            #pragma unroll
            for (int n = 0; n < 16; n++) r += s_w[b*16+n] * Mb[n * 64 + e];
            s_x[(64 + e) * 2 + b] = r;
            o_out[(((s >> 5) * 64 + (b0 + b)) * 32 + (s & 31)) * 64 + e] = s_h[e * 2 + b];
        }
        __syncthreads();
        if ((s & 31) == 31) {
            __threadfence();
            if (tid == 0) atomicExch(&g_prog[blockIdx.x], (s >> 5) + 1);
        }
    }
}

// ---------------- Decoder body (NB=2) ----------------
__device__ void dec_body(const DecP& p, int jj, float* sm)
{
    const int b0 = jj * 2;
    const int tid = threadIdx.x;

    float* s_p  = sm;            // 12288 partial union
    float* s_x  = s_p + 12288;   // 512
    float* s_h  = s_x + 512;     // 256
    float* s_gx = s_h + 256;     // 768
    float* s_gh = s_gx + 768;    // 768
    float* s_if = s_gh + 768;    // 1032
    float* s_M  = s_if + 1032;   // 4096
    float* s_c  = s_M + 4096;    // 256
    float* s_cc = s_c + 256;     // 256
    float* s_oc = s_cc + 256;    // 312
    float* s_at = s_oc + 312;    // 128
    float* s_mn = s_at + 128;    // 32
    float* s_md = s_mn + 32;     // 32
    float* s_w  = s_md + 32;     // 32
    float* s_kn = s_w + 32;      // 8

    float* p_wx = s_p;           // 8 x 768
    float* p_wh = s_p + 6144;    // 4 x 768
    float* p_if = s_p;           // 4 x 1032
    float* p_oh = s_p + 4224;    // 4 x 312
    float* p_cb = s_p;           // 4 x 256 (per-v)
    float* p_oc = s_p + 1024;    // 4 x 312 (per-v)

    for (int i = tid; i < 512; i += 768) s_x[i] = 0.f;
    for (int i = tid; i < 4096; i += 768) s_M[i] = 0.f;
    __syncthreads();

    if (tid == 0) {
        while (*(volatile int*)&g_prog[jj] < 1 || *(volatile int*)&g_prog[32 + jj] < 1)
            __nanosleep(200);
    }
    __syncthreads();
    if (tid < 256) {
        int b = tid & 1, e = tid >> 1;
        float h = (e < 64) ? g_o1[((b0 + b) * 32 + 31) * 64 + e]
                           : g_o2[((b0 + b) * 32 + 31) * 64 + (e - 64)];
        s_h[e * 2 + b] = h;
    }
    __syncthreads();

    const int c8 = tid & 7;
    const int pq = tid >> 3;
    const int pb = pq >> 4;
    float* Mp = s_M + pq * 128 + c8 * 16;

    for (int s = 0; s < 400; ++s) {
        const int v = s / 25, pos = s - v * 25;

        if (pos == 0) {
            if (tid == 0) {
                while (*(volatile int*)&g_prog[jj] <= v || *(volatile int*)&g_prog[32 + jj] <= v)
                    __nanosleep(200);
            }
            __syncthreads();
            // V0: attention scores
            if (tid < 256) {
                int cc = tid & 1, g = tid >> 1;
                int a = g >> 6, b = (g >> 5) & 1, l = g & 31;
                const float* op = (a ? g_o2 : g_o1) + ((v * 64 + (b0 + b)) * 32 + l) * 64 + cc * 32;
                const float* aw = (a ? p.attn1 : p.attn0) + 128 + cc * 32;
                float sc = 0.f;
                #pragma unroll
                for (int e = 0; e < 32; e++) sc += op[e] * __ldg(aw + e);
                sc += __shfl_down_sync(0xffffffffu, sc, 1);
                if (cc == 0) s_at[g] = sc;
            }
            __syncthreads();
            // V1: softmax
            if (tid < 128) {
                int w = tid >> 5, l = tid & 31;
                float vsc = s_at[w * 32 + l];
                float mx = vsc;
                for (int d = 16; d > 0; d >>= 1) mx = fmaxf(mx, __shfl_xor_sync(0xffffffffu, mx, d));
                float e2 = expf(vsc - mx);
                float sum = e2;
                for (int d = 16; d > 0; d >>= 1) sum += __shfl_xor_sync(0xffffffffu, sum, d);
                s_at[w * 32 + l] = e2 / sum;
            }
            __syncthreads();
            // V2: contexts
            if (tid < 256) {
                int a = tid >> 7, b = (tid >> 6) & 1, e = tid & 63;
                const float* op = (a ? g_o2 : g_o1) + ((v * 64 + (b0 + b)) * 32) * 64 + e;
                const float* at = s_at + a * 64 + b * 32;
                float cv = 0.f;
                #pragma unroll
                for (int l = 0; l < 32; l++) cv += at[l] * op[l * 64];
                s_c[(a * 64 + e) * 2 + b] = cv;
            }
            __syncthreads();
            // V3: comb_cc + out_cc partials
            if (tid < 128) {
                int jq = tid & 31, kq = tid >> 5;
                u64 a0 = 0, a1 = 0, a2 = 0, a3 = 0;
                const float* wb = p.combw + (64 + kq * 32) * 128 + jq * 4;
                const u64* xb = (const u64*)(s_c + kq * 64);
                #pragma unroll
                for (int i = 0; i < 32; i++) {
                    float4 w = __ldg((const float4*)(wb + i * 128));
                    u64 x2 = xb[i];
                    fma2(a0, bc2(w.x), x2); fma2(a1, bc2(w.y), x2);
                    fma2(a2, bc2(w.z), x2); fma2(a3, bc2(w.w), x2);
                }
                u64* d = (u64*)(p_cb + kq * 256 + jq * 8);
                d[0] = a0; d[1] = a1; d[2] = a2; d[3] = a3;
            } else if (tid < 284) {
                int u = tid - 128;
                int jq = u % 39, kq = u / 39;
                u64 a0 = 0, a1 = 0, a2 = 0, a3 = 0;
                const float* wb = g_outw_pad + (128 + kq * 32) * 156 + jq * 4;
                const u64* xb = (const u64*)(s_c + kq * 64);
                #pragma unroll
                for (int i = 0; i < 32; i++) {
                    float4 w = *(const float4*)(wb + i * 156);
                    u64 x2 = xb[i];
                    fma2(a0, bc2(w.x), x2); fma2(a1, bc2(w.y), x2);
                    fma2(a2, bc2(w.z), x2); fma2(a3, bc2(w.w), x2);
                }
                u64* d = (u64*)(p_oc + kq * 312 + jq * 8);
                d[0] = a0; d[1] = a1; d[2] = a2; d[3] = a3;
            }
            __syncthreads();
            // V4: reduce
            if (tid < 256) {
                float a = __ldg(p.combb + (tid >> 1));
                #pragma unroll
                for (int kq = 0; kq < 4; kq++) a += p_cb[kq * 256 + tid];
                s_cc[tid] = a;
            } else if (tid < 568) {
                int idx = tid - 256;
                int j = idx >> 1;
                float a = (j < 153) ? __ldg(p.outb + j) : 0.f;
                #pragma unroll
                for (int kq = 0; kq < 4; kq++) a += p_oc[kq * 312 + idx];
                s_oc[idx] = a;
            }
            __syncthreads();
        }

        // A: comb via token table + wh partials
        if (tid < 256) {
            int b = tid & 1, j = tid >> 1;
            int tok = (pos == 0) ? ((v == 0) ? 150 : 151)
                                 : p.targets[((b0 + b) * 16 + v) * 24 + (pos - 1)];
            s_x[tid] = fmaxf(__ldg(g_tbl + tok * 128 + j) + s_cc[tid], 0.f);
        } else if (tid < 640) {
            int u = tid - 256;
            int jq = u % 96, kq = u / 96;
            u64 a0 = 0, a1 = 0, a2 = 0, a3 = 0;
            const float* wb = p.wh + kq * 32 * 384 + jq * 4;
            const u64* xb = (const u64*)(s_h + kq * 64);
            #pragma unroll
            for (int i = 0; i < 32; i++) {
                float4 w = __ldg((const float4*)(wb + i * 384));
                u64 x2 = xb[i];
                fma2(a0, bc2(w.x), x2); fma2(a1, bc2(w.y), x2);
                fma2(a2, bc2(w.z), x2); fma2(a3, bc2(w.w), x2);
            }
            u64* d = (u64*)(p_wh + kq * 768 + jq * 8);
            d[0] = a0; d[1] = a1; d[2] = a2; d[3] = a3;
        }
        __syncthreads();
        // B: wx partials
        {
            int jq = tid % 96, kq = tid / 96;
            u64 a0 = 0, a1 = 0, a2 = 0, a3 = 0;
            const float* wb = p.wx + kq * 32 * 384 + jq * 4;
            const u64* xb = (const u64*)(s_x + kq * 64);
            #pragma unroll
            for (int i = 0; i < 32; i++) {
                float4 w = __ldg((const float4*)(wb + i * 384));
                u64 x2 = xb[i];
                fma2(a0, bc2(w.x), x2); fma2(a1, bc2(w.y), x2);
                fma2(a2, bc2(w.z), x2); fma2(a3, bc2(w.w), x2);
            }
            u64* d = (u64*)(p_wx + kq * 768 + jq * 8);
            d[0] = a0; d[1] = a1; d[2] = a2; d[3] = a3;
        }
        __syncthreads();
        // C1: reduce gx/gh
        {
            float a = __ldg(p.bx + (tid >> 1));
            float g = __ldg(p.bh + (tid >> 1));
            #pragma unroll
            for (int kq = 0; kq < 8; kq++) a += p_wx[kq * 768 + tid];
            #pragma unroll
            for (int kq = 0; kq < 4; kq++) g += p_wh[kq * 768 + tid];
            s_gx[tid] = a; s_gh[tid] = g;
        }
        __syncthreads();
        // C2: GRU
        if (tid < 256) {
            int b = tid & 1, j = tid >> 1;
            float xr = s_gx[j*2+b], xz = s_gx[(128+j)*2+b], xn = s_gx[(256+j)*2+b];
            float hr = s_gh[j*2+b], hz = s_gh[(128+j)*2+b], hn = s_gh[(256+j)*2+b];
            float rg = sigf(xr + hr), z = sigf(xz + hz);
            float n = tanhf(xn + rg * hn);
            s_h[j*2+b] = (1.0f - z) * n + z * s_h[j*2+b];
        }
        __syncthreads();
        // D: wi + outw(h2) partials
        if (tid < 516) {
            int jq = tid % 129, kq = tid / 129;
            u64 a0 = 0, a1 = 0, a2 = 0, a3 = 0;
            const float* wb = g_wi_pad + kq * 32 * 516 + jq * 4;
            const u64* xb = (const u64*)(s_h + kq * 64);
            #pragma unroll
            for (int i = 0; i < 32; i++) {
                float4 w = *(const float4*)(wb + i * 516);
                u64 x2 = xb[i];
                fma2(a0, bc2(w.x), x2); fma2(a1, bc2(w.y), x2);
                fma2(a2, bc2(w.z), x2); fma2(a3, bc2(w.w), x2);
            }
            u64* d = (u64*)(p_if + kq * 1032 + jq * 8);
            d[0] = a0; d[1] = a1; d[2] = a2; d[3] = a3;
        } else if (tid < 672) {
            int u = tid - 516;
            int jq = u % 39, kq = u / 39;
            u64 a0 = 0, a1 = 0, a2 = 0, a3 = 0;
            const float* wb = g_outw_pad + kq * 32 * 156 + jq * 4;
            const u64* xb = (const u64*)(s_h + kq * 64);
            #pragma unroll
            for (int i = 0; i < 32; i++) {
                float4 w = *(const float4*)(wb + i * 156);
                u64 x2 = xb[i];
                fma2(a0, bc2(w.x), x2); fma2(a1, bc2(w.y), x2);
                fma2(a2, bc2(w.z), x2); fma2(a3, bc2(w.w), x2);
            }
            u64* d = (u64*)(p_oh + kq * 312 + jq * 8);
            d[0] = a0; d[1] = a1; d[2] = a2; d[3] = a3;
        }
        __syncthreads();
        // E: reduce iface + logits store
        for (int u = tid; u < 1030; u += 768) {
            float a = __ldg(p.bi + (u >> 1));
            #pragma unroll
            for (int kq = 0; kq < 4; kq++) a += p_if[kq * 1032 + u];
            s_if[u] = a;
        }
        if (tid < 306) {
            int j = tid >> 1, b = tid & 1;
            float a = s_oc[tid];
            #pragma unroll
            for (int kq = 0; kq < 4; kq++) a += p_oh[kq * 312 + tid];
            p.out[((b0 + b) * 400 + s) * 153 + j] = a;
        }
        __syncthreads();
        // F: M pre-stats + key norms
        if (tid < 256) {
            float ss = 0.f, dw = 0.f;
            #pragma unroll
            for (int i = 0; i < 16; i++) {
                float m = Mp[i];
                ss += m * m; dw += m * s_if[(128 + c8 * 16 + i) * 2 + pb];
            }
            for (int d = 4; d > 0; d >>= 1) {
                ss += __shfl_down_sync(0xffffffffu, ss, d);
                dw += __shfl_down_sync(0xffffffffu, dw, d);
            }
            if (c8 == 0) { s_mn[pq] = sqrtf(ss); s_md[pq] = dw; }
        } else if (tid < 384) {
            int w = (tid >> 5) - 8, lane = tid & 31;
            int b = w & 1, isr = w >> 1;
            int base = isr ? 0 : 128;
            float t2 = 0.f;
            #pragma unroll
            for (int q = 0; q < 4; q++) {
                float vq = s_if[(base + lane + q * 32) * 2 + b];
                t2 += vq * vq;
            }
            for (int d = 16; d > 0; d >>= 1) t2 += __shfl_down_sync(0xffffffffu, t2, d);
            if (lane == 0) s_kn[isr * 2 + b] = sqrtf(t2);
        }
        __syncthreads();
        // G: ww softmax
        if (tid < 64 && (tid & 31) < 16) {
            int b = tid >> 5, n = tid & 15;
            float bw = softplusf(s_if[513*2+b]) + 1.0f;
            float gw = sigf(s_if[514*2+b]);
            float kn = s_kn[0*2+b];
            float sc = bw * (s_md[b*16+n] / (s_mn[b*16+n] * kn + 1e-6f));
            float mx = sc;
            for (int d = 8; d > 0; d >>= 1) mx = fmaxf(mx, __shfl_xor_sync(0xffffu, mx, d));
            float e = expf(sc - mx);
            float sum = e;
            for (int d = 8; d > 0; d >>= 1) sum += __shfl_xor_sync(0xffffu, sum, d);
            s_w[b*16+n] = e * (gw / sum);
        }
        __syncthreads();
        // H: M update + post stats
        if (tid < 256) {
            float wwv = s_w[pq], ss = 0.f, dr = 0.f;
            #pragma unroll
            for (int i = 0; i < 16; i++) {
                int e = c8 * 16 + i;
                float er = sigf(s_if[(256 + e) * 2 + pb]);
                float wv = s_if[(384 + e) * 2 + pb];
                float m = Mp[i];
                m = m * (1.0f - wwv * er) + wwv * wv;
                Mp[i] = m;
                ss += m * m; dr += m * s_if[e * 2 + pb];
            }
            for (int d = 4; d > 0; d >>= 1) {
                ss += __shfl_down_sync(0xffffffffu, ss, d);
                dr += __shfl_down_sync(0xffffffffu, dr, d);
            }
            if (c8 == 0) { s_mn[pq] = sqrtf(ss); s_md[pq] = dr; }
        }
        __syncthreads();
        // I: wr softmax
        if (tid < 64 && (tid & 31) < 16) {
            int b = tid >> 5, n = tid & 15;
            float br = softplusf(s_if[512*2+b]) + 1.0f;
            float kn = s_kn[1*2+b];
            float sc = br * (s_md[b*16+n] / (s_mn[b*16+n] * kn + 1e-6f));
            float mx = sc;
            for (int d = 8; d > 0; d >>= 1) mx = fmaxf(mx, __shfl_xor_sync(0xffffu, mx, d));
            float e = expf(sc - mx);
            float sum = e;
            for (int d = 8; d > 0; d >>= 1) sum += __shfl_xor_sync(0xffffu, sum, d);
            s_w[b*16+n] = e / sum;
        }
        __syncthreads();
        // J: r = wr@M
        if (tid < 256) {
            int b = tid & 1, e = tid >> 1;
            const float* Mb = s_M + b * 2048;
            float r = 0.f;
            #pragma unroll
            for (int n = 0; n < 16; n++) r += s_w[b*16+n] * Mb[n * 128 + e];
            s_x[(128 + e) * 2 + b] = r;
        }
        __syncthreads();
    }
}

__global__ void __launch_bounds__(768, 1)
fused_kernel(EncP P0, EncP P1, DecP D)
{
    extern __shared__ float sm[];
    int bid = blockIdx.x;
    if (bid < 64) {
        const EncP& p = (bid < 32) ? P0 : P1;
        float* o_out = (bid < 32) ? g_o1 : g_o2;
        enc_body(p, o_out, (bid & 31) * 2, sm);
    } else {
        dec_body(D, bid - 64, sm);
    }
}

// ======= labels + tail copies =======
__global__ void tail_kernel(const int* __restrict__ targets, float* __restrict__ out)
{
    int idx = blockIdx.x * blockDim.x + threadIdx.x;
    if (idx < 25600) {
        int b = idx / 400, ss = idx % 400;
        int t = ss / 25, j = ss % 25;
        float val = (j < 24) ? (float)targets[(b * 16 + t) * 24 + j]
                             : ((t == 15) ? 152.0f : 151.0f);
        out[3916800 + idx] = val;
        if (ss >= 375) out[4187200 + b * 25 + (ss - 375)] = val;
    }
    if (idx < 244800) {
        int b = idx / 3825, rem = idx % 3825;
        out[3942400 + idx] = out[(b * 400 + 375) * 153 + rem];
    }
}

extern "C" void kernel_launch(void* const* d_in, const int* in_sizes, int n_in,
                              void* d_out, int out_size)
{
    (void)in_sizes; (void)n_in; (void)out_size;
    const int*   codes1 = (const int*)d_in[0];
    const int*   codes2 = (const int*)d_in[1];
    const int*   targets= (const int*)d_in[2];

    EncP P0 { codes1, (const float*)d_in[3], (const float*)d_in[6],  (const float*)d_in[7],
              (const float*)d_in[8],  (const float*)d_in[9],
              (const float*)d_in[10], (const float*)d_in[11] };
    EncP P1 { codes2, (const float*)d_in[4], (const float*)d_in[12], (const float*)d_in[13],
              (const float*)d_in[14], (const float*)d_in[15],
              (const float*)d_in[16], (const float*)d_in[17] };
    DecP D  { targets,
              (const float*)d_in[18], (const float*)d_in[19],
              (const float*)d_in[20], (const float*)d_in[21],
              (const float*)d_in[23],
              (const float*)d_in[24], (const float*)d_in[25],
              (const float*)d_in[26], (const float*)d_in[27],
              (const float*)d_in[29],
              (float*)d_out };

    static bool attr_done = false;
    if (!attr_done) {
        cudaFuncSetAttribute(fused_kernel, cudaFuncAttributeMaxDynamicSharedMemorySize, 164320);
        attr_done = true;
    }

    prep_kernel<<<259, 256>>>((const float*)d_in[22], (const float*)d_in[28],
                              (const float*)d_in[5], (const float*)d_in[26]);
    fused_kernel<<<96, 768, 164320>>>(P0, P1, D);
    tail_kernel<<<(244800 + 255) / 256, 256>>>(targets, (float*)d_out);
}